// round 1
// baseline (speedup 1.0000x reference)
#include <cuda_runtime.h>
#include <math.h>

#define TTOK 8192
#define DM   512
#define QKVN 1536
#define HFF  2048
#define NE   8
#define NSEQ 1024
#define NHEAD 8
#define DH   64
#define NL   4
#define SLOTMAX (2*TTOK + NE*128)   /* 17408 */
#define MAXRB   (SLOTMAX/128)       /* 136   */

// ---------------- static device scratch (no allocations allowed) ----------------
__device__ __align__(128) float g_x[TTOK*DM];
__device__ __align__(128) float g_y[TTOK*DM];
__device__ __align__(128) float g_qkv[TTOK*QKVN];
__device__ __align__(128) float g_attn[TTOK*DM];
__device__ __align__(128) float g_scores[(size_t)64*NSEQ*NSEQ];
__device__ __align__(128) float g_h[(size_t)SLOTMAX*HFF];
__device__ __align__(128) float g_y2[(size_t)SLOTMAX*DM];
__device__ __align__(128) float g_logits[TTOK*NE];
__device__ int   g_e0[TTOK], g_e1[TTOK];
__device__ float g_g0[TTOK], g_g1[TTOK];
__device__ int   g_cnt[NE], g_off[NE], g_cur[NE];
__device__ int   g_map[MAXRB];
__device__ int   g_tok[SLOTMAX];
__device__ int   g_slotA[TTOK], g_slotB[TTOK];

// ---------------- helpers ----------------
__global__ void k_copy4(const float4* __restrict__ in, float4* __restrict__ out, int n4){
    int i = blockIdx.x*blockDim.x + threadIdx.x;
    if (i < n4) out[i] = in[i];
}

// LayerNorm: one block (128 threads) per token row of 512
__global__ void k_ln(const float* __restrict__ in, float* __restrict__ out,
                     const float* __restrict__ w, const float* __restrict__ b){
    int t = blockIdx.x;
    int i = threadIdx.x;                      // 0..127, 4 floats each
    float4 v = ((const float4*)(in + (size_t)t*DM))[i];
    float s  = v.x+v.y+v.z+v.w;
    float ss = v.x*v.x+v.y*v.y+v.z*v.z+v.w*v.w;
    #pragma unroll
    for (int o=16;o;o>>=1){ s += __shfl_xor_sync(0xffffffffu,s,o); ss += __shfl_xor_sync(0xffffffffu,ss,o); }
    __shared__ float sh_s[4], sh_q[4];
    int wid = i>>5, lane = i&31;
    if (lane==0){ sh_s[wid]=s; sh_q[wid]=ss; }
    __syncthreads();
    s  = sh_s[0]+sh_s[1]+sh_s[2]+sh_s[3];
    ss = sh_q[0]+sh_q[1]+sh_q[2]+sh_q[3];
    float mean = s * (1.0f/DM);
    float var  = ss * (1.0f/DM) - mean*mean;
    float inv  = rsqrtf(var + 1e-5f);
    float4 wv = ((const float4*)w)[i];
    float4 bv = ((const float4*)b)[i];
    float4 o;
    o.x = (v.x-mean)*inv*wv.x + bv.x;
    o.y = (v.y-mean)*inv*wv.y + bv.y;
    o.z = (v.z-mean)*inv*wv.z + bv.z;
    o.w = (v.w-mean)*inv*wv.w + bv.w;
    ((float4*)(out + (size_t)t*DM))[i] = o;
}

// ---------------- generic tiled SGEMM 128x128x16, 256 thr, 8x8/thread ----------------
// MODE 0: C = A@B (+bias) ; MODE 1: C += A@B (+bias)
template<int MODE>
__global__ void __launch_bounds__(256,2) k_gemm(
        const float* __restrict__ A, int lda,
        const float* __restrict__ B, int ldb,
        float* __restrict__ C, int ldc,
        const float* __restrict__ bias, int K){
    __shared__ float As[16][128];
    __shared__ float Bs[16][128];
    const int tid = threadIdx.x;
    const int tx = tid & 15, ty = tid >> 4;
    const float* Ab = A + (size_t)blockIdx.y*128*lda;
    const float* Bb = B + blockIdx.x*128;
    const int r0  = tid>>2,  kq0 = (tid&3)*4;
    const int bk0 = tid>>5,  bc0 = (tid&31)*4;
    float acc[8][8];
    #pragma unroll
    for (int i=0;i<8;i++)
        #pragma unroll
        for (int j=0;j<8;j++) acc[i][j]=0.f;

    for (int k0=0;k0<K;k0+=16){
        float4 a0 = *(const float4*)(Ab + (size_t)r0*lda      + k0 + kq0);
        float4 a1 = *(const float4*)(Ab + (size_t)(r0+64)*lda + k0 + kq0);
        float4 b0 = *(const float4*)(Bb + (size_t)(k0+bk0  )*ldb + bc0);
        float4 b1 = *(const float4*)(Bb + (size_t)(k0+bk0+8)*ldb + bc0);
        As[kq0+0][r0]=a0.x; As[kq0+1][r0]=a0.y; As[kq0+2][r0]=a0.z; As[kq0+3][r0]=a0.w;
        As[kq0+0][r0+64]=a1.x; As[kq0+1][r0+64]=a1.y; As[kq0+2][r0+64]=a1.z; As[kq0+3][r0+64]=a1.w;
        *(float4*)&Bs[bk0  ][bc0] = b0;
        *(float4*)&Bs[bk0+8][bc0] = b1;
        __syncthreads();
        #pragma unroll
        for (int k=0;k<16;k++){
            float ar[8], br[8];
            *(float4*)(ar)   = *(const float4*)&As[k][ty*8];
            *(float4*)(ar+4) = *(const float4*)&As[k][ty*8+4];
            *(float4*)(br)   = *(const float4*)&Bs[k][tx*8];
            *(float4*)(br+4) = *(const float4*)&Bs[k][tx*8+4];
            #pragma unroll
            for (int i=0;i<8;i++)
                #pragma unroll
                for (int j=0;j<8;j++)
                    acc[i][j] = fmaf(ar[i], br[j], acc[i][j]);
        }
        __syncthreads();
    }
    #pragma unroll
    for (int i=0;i<8;i++){
        float* Crow = C + (size_t)(blockIdx.y*128 + ty*8 + i)*ldc + blockIdx.x*128 + tx*8;
        #pragma unroll
        for (int j=0;j<8;j+=4){
            float4 v; v.x=acc[i][j]; v.y=acc[i][j+1]; v.z=acc[i][j+2]; v.w=acc[i][j+3];
            if (bias){
                float4 bb = *(const float4*)(bias + blockIdx.x*128 + tx*8 + j);
                v.x+=bb.x; v.y+=bb.y; v.z+=bb.z; v.w+=bb.w;
            }
            if (MODE==1){
                float4 c = *(float4*)(Crow+j);
                v.x+=c.x; v.y+=c.y; v.z+=c.z; v.w+=c.w;
            }
            *(float4*)(Crow+j) = v;
        }
    }
}

// ---------------- MoE GEMM (static grid, expert map, optional gather + GELU) ----------------
template<int KD,int ND,int GELU,int GATHER>
__global__ void __launch_bounds__(256,2) k_moe_gemm(
        const float* __restrict__ Abase,
        const float* __restrict__ Ball,      // [E][KD][ND] for this layer
        const float* __restrict__ Biasall,   // [E][ND]
        float* __restrict__ C){              // [SLOTMAX][ND]
    const int rb = blockIdx.y;
    const int e  = g_map[rb];
    if (e < 0) return;
    const float* B    = Ball    + (size_t)e*KD*ND + blockIdx.x*128;
    const float* bias = Biasall + (size_t)e*ND    + blockIdx.x*128;

    __shared__ float As[16][128];
    __shared__ float Bs[16][128];
    const int tid = threadIdx.x;
    const int tx = tid & 15, ty = tid >> 4;
    const int r0  = tid>>2,  kq0 = (tid&3)*4;
    const int bk0 = tid>>5,  bc0 = (tid&31)*4;

    const float *Ar0, *Ar1;
    if (GATHER){
        int lim = g_off[e] + g_cnt[e];
        int s0 = rb*128 + r0, s1 = s0 + 64;
        Ar0 = (s0 < lim) ? Abase + (size_t)g_tok[s0]*KD : (const float*)0;
        Ar1 = (s1 < lim) ? Abase + (size_t)g_tok[s1]*KD : (const float*)0;
    } else {
        Ar0 = Abase + (size_t)(rb*128 + r0     )*KD;
        Ar1 = Abase + (size_t)(rb*128 + r0 + 64)*KD;
    }

    float acc[8][8];
    #pragma unroll
    for (int i=0;i<8;i++)
        #pragma unroll
        for (int j=0;j<8;j++) acc[i][j]=0.f;

    for (int k0=0;k0<KD;k0+=16){
        float4 a0 = Ar0 ? *(const float4*)(Ar0 + k0 + kq0) : make_float4(0.f,0.f,0.f,0.f);
        float4 a1 = Ar1 ? *(const float4*)(Ar1 + k0 + kq0) : make_float4(0.f,0.f,0.f,0.f);
        float4 b0 = *(const float4*)(B + (size_t)(k0+bk0  )*ND + bc0);
        float4 b1 = *(const float4*)(B + (size_t)(k0+bk0+8)*ND + bc0);
        As[kq0+0][r0]=a0.x; As[kq0+1][r0]=a0.y; As[kq0+2][r0]=a0.z; As[kq0+3][r0]=a0.w;
        As[kq0+0][r0+64]=a1.x; As[kq0+1][r0+64]=a1.y; As[kq0+2][r0+64]=a1.z; As[kq0+3][r0+64]=a1.w;
        *(float4*)&Bs[bk0  ][bc0] = b0;
        *(float4*)&Bs[bk0+8][bc0] = b1;
        __syncthreads();
        #pragma unroll
        for (int k=0;k<16;k++){
            float ar[8], br[8];
            *(float4*)(ar)   = *(const float4*)&As[k][ty*8];
            *(float4*)(ar+4) = *(const float4*)&As[k][ty*8+4];
            *(float4*)(br)   = *(const float4*)&Bs[k][tx*8];
            *(float4*)(br+4) = *(const float4*)&Bs[k][tx*8+4];
            #pragma unroll
            for (int i=0;i<8;i++)
                #pragma unroll
                for (int j=0;j<8;j++)
                    acc[i][j] = fmaf(ar[i], br[j], acc[i][j]);
        }
        __syncthreads();
    }
    #pragma unroll
    for (int i=0;i<8;i++){
        float* Crow = C + (size_t)(rb*128 + ty*8 + i)*ND + blockIdx.x*128 + tx*8;
        #pragma unroll
        for (int j=0;j<8;j+=4){
            float4 bb = *(const float4*)(bias + tx*8 + j);
            float4 v; v.x=acc[i][j]+bb.x; v.y=acc[i][j+1]+bb.y; v.z=acc[i][j+2]+bb.z; v.w=acc[i][j+3]+bb.w;
            if (GELU){
                v.x = 0.5f*v.x*(1.f+erff(v.x*0.70710678118654752f));
                v.y = 0.5f*v.y*(1.f+erff(v.y*0.70710678118654752f));
                v.z = 0.5f*v.z*(1.f+erff(v.z*0.70710678118654752f));
                v.w = 0.5f*v.w*(1.f+erff(v.w*0.70710678118654752f));
            }
            *(float4*)(Crow+j) = v;
        }
    }
}

// ---------------- attention: scores = Q @ K^T * scale (batched over b*h) ----------------
__global__ void __launch_bounds__(256,2) k_scores(const float* __restrict__ qkv){
    const int bh = blockIdx.z;
    const int b = bh>>3, h = bh&7;
    const float* Q  = qkv + (size_t)b*NSEQ*QKVN + h*DH;
    const float* Kp = Q + 512;                 // +INNER
    float* C = g_scores + (size_t)bh*NSEQ*NSEQ;

    __shared__ float As[16][128];
    __shared__ float Bs[16][128];
    const int tid = threadIdx.x;
    const int tx = tid & 15, ty = tid >> 4;
    const int r0 = tid>>2, kq0 = (tid&3)*4;
    const int c0 = tid>>2, ck0 = (tid&3)*4;

    float acc[8][8];
    #pragma unroll
    for (int i=0;i<8;i++)
        #pragma unroll
        for (int j=0;j<8;j++) acc[i][j]=0.f;

    for (int k0=0;k0<DH;k0+=16){
        float4 a0 = *(const float4*)(Q + (size_t)(blockIdx.y*128 + r0     )*QKVN + k0 + kq0);
        float4 a1 = *(const float4*)(Q + (size_t)(blockIdx.y*128 + r0 + 64)*QKVN + k0 + kq0);
        float4 t0 = *(const float4*)(Kp + (size_t)(blockIdx.x*128 + c0     )*QKVN + k0 + ck0);
        float4 t1 = *(const float4*)(Kp + (size_t)(blockIdx.x*128 + c0 + 64)*QKVN + k0 + ck0);
        As[kq0+0][r0]=a0.x; As[kq0+1][r0]=a0.y; As[kq0+2][r0]=a0.z; As[kq0+3][r0]=a0.w;
        As[kq0+0][r0+64]=a1.x; As[kq0+1][r0+64]=a1.y; As[kq0+2][r0+64]=a1.z; As[kq0+3][r0+64]=a1.w;
        Bs[ck0+0][c0]=t0.x; Bs[ck0+1][c0]=t0.y; Bs[ck0+2][c0]=t0.z; Bs[ck0+3][c0]=t0.w;
        Bs[ck0+0][c0+64]=t1.x; Bs[ck0+1][c0+64]=t1.y; Bs[ck0+2][c0+64]=t1.z; Bs[ck0+3][c0+64]=t1.w;
        __syncthreads();
        #pragma unroll
        for (int k=0;k<16;k++){
            float ar[8], br[8];
            *(float4*)(ar)   = *(const float4*)&As[k][ty*8];
            *(float4*)(ar+4) = *(const float4*)&As[k][ty*8+4];
            *(float4*)(br)   = *(const float4*)&Bs[k][tx*8];
            *(float4*)(br+4) = *(const float4*)&Bs[k][tx*8+4];
            #pragma unroll
            for (int i=0;i<8;i++)
                #pragma unroll
                for (int j=0;j<8;j++)
                    acc[i][j] = fmaf(ar[i], br[j], acc[i][j]);
        }
        __syncthreads();
    }
    const float scale = 0.125f;   // 64^-0.5
    #pragma unroll
    for (int i=0;i<8;i++){
        float* Crow = C + (size_t)(blockIdx.y*128 + ty*8 + i)*NSEQ + blockIdx.x*128 + tx*8;
        #pragma unroll
        for (int j=0;j<8;j+=4){
            float4 v; v.x=acc[i][j]*scale; v.y=acc[i][j+1]*scale; v.z=acc[i][j+2]*scale; v.w=acc[i][j+3]*scale;
            *(float4*)(Crow+j) = v;
        }
    }
}

// row softmax over 1024, one block (256 thr) per row
__global__ void k_softmax(){
    float* row = g_scores + (size_t)blockIdx.x*NSEQ;
    int i = threadIdx.x;
    float4 v = ((float4*)row)[i];
    float m = fmaxf(fmaxf(v.x,v.y), fmaxf(v.z,v.w));
    #pragma unroll
    for (int o=16;o;o>>=1) m = fmaxf(m, __shfl_xor_sync(0xffffffffu,m,o));
    __shared__ float sh[8];
    int wid = i>>5, lane = i&31;
    if (lane==0) sh[wid]=m;
    __syncthreads();
    float bm = sh[0];
    #pragma unroll
    for (int w=1;w<8;w++) bm = fmaxf(bm, sh[w]);
    v.x = __expf(v.x-bm); v.y = __expf(v.y-bm); v.z = __expf(v.z-bm); v.w = __expf(v.w-bm);
    float s = v.x+v.y+v.z+v.w;
    #pragma unroll
    for (int o=16;o;o>>=1) s += __shfl_xor_sync(0xffffffffu,s,o);
    __syncthreads();
    if (lane==0) sh[wid]=s;
    __syncthreads();
    float bs = sh[0]+sh[1]+sh[2]+sh[3]+sh[4]+sh[5]+sh[6]+sh[7];
    float inv = 1.0f/bs;
    v.x*=inv; v.y*=inv; v.z*=inv; v.w*=inv;
    ((float4*)row)[i] = v;
}

// O = A(attn) @ V (batched, BM=128 BN=64 BK=16)
__global__ void __launch_bounds__(256,2) k_av(const float* __restrict__ qkv){
    const int bh = blockIdx.z;
    const int b = bh>>3, h = bh&7;
    const float* A = g_scores + (size_t)bh*NSEQ*NSEQ;
    const float* V = qkv + (size_t)b*NSEQ*QKVN + 1024 + h*DH;   // +2*INNER
    float* C = g_attn + (size_t)b*NSEQ*DM + h*DH;

    __shared__ float As[16][128];
    __shared__ float Bs[16][64];
    const int tid = threadIdx.x;
    const int tx = tid & 15, ty = tid >> 4;
    const int r0 = tid>>2, kq0 = (tid&3)*4;
    const int bk0 = tid>>4, bc0 = (tid&15)*4;
    const int arow = blockIdx.y*128;

    float acc[8][4];
    #pragma unroll
    for (int i=0;i<8;i++)
        #pragma unroll
        for (int j=0;j<4;j++) acc[i][j]=0.f;

    for (int k0=0;k0<NSEQ;k0+=16){
        float4 a0 = *(const float4*)(A + (size_t)(arow+r0   )*NSEQ + k0 + kq0);
        float4 a1 = *(const float4*)(A + (size_t)(arow+r0+64)*NSEQ + k0 + kq0);
        float4 bv = *(const float4*)(V + (size_t)(k0+bk0)*QKVN + bc0);
        As[kq0+0][r0]=a0.x; As[kq0+1][r0]=a0.y; As[kq0+2][r0]=a0.z; As[kq0+3][r0]=a0.w;
        As[kq0+0][r0+64]=a1.x; As[kq0+1][r0+64]=a1.y; As[kq0+2][r0+64]=a1.z; As[kq0+3][r0+64]=a1.w;
        *(float4*)&Bs[bk0][bc0] = bv;
        __syncthreads();
        #pragma unroll
        for (int k=0;k<16;k++){
            float ar[8], br[4];
            *(float4*)(ar)   = *(const float4*)&As[k][ty*8];
            *(float4*)(ar+4) = *(const float4*)&As[k][ty*8+4];
            *(float4*)(br)   = *(const float4*)&Bs[k][tx*4];
            #pragma unroll
            for (int i=0;i<8;i++)
                #pragma unroll
                for (int j=0;j<4;j++)
                    acc[i][j] = fmaf(ar[i], br[j], acc[i][j]);
        }
        __syncthreads();
    }
    #pragma unroll
    for (int i=0;i<8;i++){
        float4 v; v.x=acc[i][0]; v.y=acc[i][1]; v.z=acc[i][2]; v.w=acc[i][3];
        *(float4*)(C + (size_t)(arow + ty*8 + i)*DM + tx*4) = v;
    }
}

// ---------------- MoE routing ----------------
__global__ void k_gate(const float* __restrict__ wg){   // wg: [DM][NE] for this layer
    int gid = blockIdx.x*blockDim.x + threadIdx.x;
    if (gid >= TTOK*NE) return;
    int t = gid>>3, e = gid&7;
    const float* xr = g_y + (size_t)t*DM;
    float s = 0.f;
    #pragma unroll 8
    for (int k=0;k<DM;k++) s = fmaf(xr[k], wg[k*NE+e], s);
    g_logits[t*NE+e] = s;
}

__global__ void k_zero_cnt(){ if (threadIdx.x < NE) g_cnt[threadIdx.x] = 0; }

__global__ void k_top2(){
    int t = blockIdx.x*blockDim.x + threadIdx.x;
    if (t >= TTOK) return;
    const float* lr = g_logits + t*NE;
    int i0 = 0; float v0 = lr[0];
    #pragma unroll
    for (int e=1;e<NE;e++){ float v = lr[e]; if (v > v0){ v0=v; i0=e; } }
    int i1 = -1; float v1 = -3.4e38f;
    #pragma unroll
    for (int e=0;e<NE;e++){ if (e==i0) continue; float v = lr[e]; if (v > v1){ v1=v; i1=e; } }
    float e1v = expf(v1 - v0);
    float inv = 1.0f/(1.0f + e1v);
    g_e0[t]=i0; g_e1[t]=i1;
    g_g0[t]=inv; g_g1[t]=e1v*inv;
    atomicAdd(&g_cnt[i0],1);
    atomicAdd(&g_cnt[i1],1);
}

__global__ void k_scan(){
    int off = 0, rb = 0;
    for (int e=0;e<NE;e++){
        g_off[e] = off; g_cur[e] = off;
        int nb = (g_cnt[e] + 127) >> 7;
        for (int i=0;i<nb;i++) g_map[rb++] = e;
        off += nb*128;
    }
    for (; rb<MAXRB; rb++) g_map[rb] = -1;
}

__global__ void k_scatter(){
    int t = blockIdx.x*blockDim.x + threadIdx.x;
    if (t >= TTOK) return;
    int p0 = atomicAdd(&g_cur[g_e0[t]], 1); g_tok[p0]=t; g_slotA[t]=p0;
    int p1 = atomicAdd(&g_cur[g_e1[t]], 1); g_tok[p1]=t; g_slotB[t]=p1;
}

__global__ void k_combine(){   // x[t] += g0*y2[slotA] + g1*y2[slotB]
    int t = blockIdx.x, i = threadIdx.x;   // 128 thr, float4
    float gg0 = g_g0[t], gg1 = g_g1[t];
    float4 a = ((const float4*)(g_y2 + (size_t)g_slotA[t]*DM))[i];
    float4 b = ((const float4*)(g_y2 + (size_t)g_slotB[t]*DM))[i];
    float4* xr = (float4*)(g_x + (size_t)t*DM);
    float4 xv = xr[i];
    xv.x += gg0*a.x + gg1*b.x;
    xv.y += gg0*a.y + gg1*b.y;
    xv.z += gg0*a.z + gg1*b.z;
    xv.w += gg0*a.w + gg1*b.w;
    xr[i] = xv;
}

// ---------------- host orchestration ----------------
extern "C" void kernel_launch(void* const* d_in, const int* in_sizes, int n_in,
                              void* d_out, int out_size){
    (void)in_sizes; (void)n_in; (void)out_size;
    const float* x    = (const float*)d_in[0];
    const float* ln1w = (const float*)d_in[1];
    const float* ln1b = (const float*)d_in[2];
    const float* qkvw = (const float*)d_in[3];
    const float* outw = (const float*)d_in[4];
    const float* outb = (const float*)d_in[5];
    const float* ln2w = (const float*)d_in[6];
    const float* ln2b = (const float*)d_in[7];
    const float* wg   = (const float*)d_in[8];
    const float* ew1  = (const float*)d_in[9];
    const float* eb1  = (const float*)d_in[10];
    const float* ew2  = (const float*)d_in[11];
    const float* eb2  = (const float*)d_in[12];
    const float* flnw = (const float*)d_in[13];
    const float* flnb = (const float*)d_in[14];
    float* out = (float*)d_out;

    float *px, *py, *pq, *pa, *ph, *py2;
    cudaGetSymbolAddress((void**)&px,  g_x);
    cudaGetSymbolAddress((void**)&py,  g_y);
    cudaGetSymbolAddress((void**)&pq,  g_qkv);
    cudaGetSymbolAddress((void**)&pa,  g_attn);
    cudaGetSymbolAddress((void**)&ph,  g_h);
    cudaGetSymbolAddress((void**)&py2, g_y2);

    // x -> g_x
    {
        int n4 = TTOK*DM/4;
        k_copy4<<<(n4+255)/256, 256>>>((const float4*)x, (float4*)px, n4);
    }

    for (int l=0;l<NL;l++){
        // attention block
        k_ln<<<TTOK,128>>>(px, py, ln1w + l*DM, ln1b + l*DM);
        k_gemm<0><<<dim3(QKVN/128, TTOK/128), 256>>>(py, DM, qkvw + (size_t)l*DM*QKVN, QKVN,
                                                     pq, QKVN, (const float*)0, DM);
        k_scores<<<dim3(NSEQ/128, NSEQ/128, 64), 256>>>(pq);
        k_softmax<<<64*NSEQ, 256>>>();
        k_av<<<dim3(1, NSEQ/128, 64), 256>>>(pq);
        k_gemm<1><<<dim3(DM/128, TTOK/128), 256>>>(pa, DM, outw + (size_t)l*DM*DM, DM,
                                                   px, DM, outb + l*DM, DM);
        // MoE block
        k_ln<<<TTOK,128>>>(px, py, ln2w + l*DM, ln2b + l*DM);
        k_zero_cnt<<<1,32>>>();
        k_gate<<<(TTOK*NE)/256, 256>>>(wg + (size_t)l*DM*NE);
        k_top2<<<TTOK/256, 256>>>();
        k_scan<<<1,1>>>();
        k_scatter<<<TTOK/256, 256>>>();
        k_moe_gemm<DM, HFF, 1, 1><<<dim3(HFF/128, MAXRB), 256>>>(
            py, ew1 + (size_t)l*NE*DM*HFF, eb1 + (size_t)l*NE*HFF, ph);
        k_moe_gemm<HFF, DM, 0, 0><<<dim3(DM/128, MAXRB), 256>>>(
            ph, ew2 + (size_t)l*NE*HFF*DM, eb2 + (size_t)l*NE*DM, py2);
        k_combine<<<TTOK,128>>>();
    }

    k_ln<<<TTOK,128>>>(px, out, flnw, flnb);
}

// round 4
// speedup vs baseline: 2.0775x; 2.0775x over previous
#include <cuda_runtime.h>
#include <cuda_bf16.h>
#include <math.h>
#include <stdint.h>

#define TTOK 8192
#define DM   512
#define QKVN 1536
#define HFF  2048
#define NE   8
#define NSEQ 1024
#define DH   64
#define NL   4
#define SLOTMAX (2*TTOK + NE*128)   /* 17408 */
#define MAXRB   (SLOTMAX/128)       /* 136   */

typedef __nv_bfloat16  bf16;
typedef __nv_bfloat162 bf162;

// ---------------- static device scratch ----------------
__device__ __align__(128) float g_x[TTOK*DM];
__device__ __align__(128) float g_y[TTOK*DM];
__device__ __align__(128) float g_qkv[(size_t)TTOK*QKVN];
__device__ __align__(128) float g_scores[(size_t)64*NSEQ*NSEQ];
__device__ __align__(128) float g_attn[TTOK*DM];
__device__ __align__(128) float g_y2[(size_t)SLOTMAX*DM];
__device__ __align__(128) float g_logits[TTOK*NE];
__device__ __align__(128) bf16  g_yh[(size_t)TTOK*3*DM];            // A-split LN out
__device__ __align__(128) bf16  g_qh[(size_t)64*NSEQ*3*DH];         // A-split Q
__device__ __align__(128) bf16  g_kh[(size_t)64*NSEQ*3*DH];         // B-split K
__device__ __align__(128) bf16  g_vth[(size_t)64*DH*3*NSEQ];        // B-split V^T
__device__ __align__(128) bf16  g_probsh[(size_t)64*NSEQ*3*NSEQ];   // A-split probs
__device__ __align__(128) bf16  g_attnsp[(size_t)TTOK*3*DM];        // A-split attn out
__device__ __align__(128) bf16  g_hh[(size_t)SLOTMAX*3*HFF];        // A-split moe hidden
__device__ __align__(128) bf16  g_qkvwT[(size_t)NL*QKVN*3*DM];      // B-split weights
__device__ __align__(128) bf16  g_outwT[(size_t)NL*DM*3*DM];
__device__ __align__(128) bf16  g_e1T[(size_t)NL*NE*HFF*3*DM];
__device__ __align__(128) bf16  g_e2T[(size_t)NL*NE*DM*3*HFF];
__device__ int   g_e0[TTOK], g_e1i[TTOK];
__device__ float g_g0[TTOK], g_g1[TTOK];
__device__ int   g_cnt[NE], g_off[NE], g_cur[NE];
__device__ int   g_map[MAXRB];
__device__ int   g_tok[SLOTMAX];
__device__ int   g_slotA[TTOK], g_slotB[TTOK];

// ---------------- low-level helpers ----------------
__device__ __forceinline__ uint32_t smem_u32(const void* p){
    uint32_t a; asm("{ .reg .u64 t; cvta.to.shared.u64 t, %1; cvt.u32.u64 %0, t; }":"=r"(a):"l"(p)); return a;
}
__device__ __forceinline__ void cpasync16(uint32_t dst, const void* src){
    asm volatile("cp.async.cg.shared.global [%0], [%1], 16;" :: "r"(dst), "l"(src));
}
#define CP_COMMIT() asm volatile("cp.async.commit_group;" ::: "memory")
#define CP_WAIT1()  asm volatile("cp.async.wait_group 1;" ::: "memory")
#define CP_WAIT0()  asm volatile("cp.async.wait_group 0;" ::: "memory")
__device__ __forceinline__ void ldm4(uint32_t* r, uint32_t a){
    asm volatile("ldmatrix.sync.aligned.m8n8.x4.shared.b16 {%0,%1,%2,%3}, [%4];"
        : "=r"(r[0]),"=r"(r[1]),"=r"(r[2]),"=r"(r[3]) : "r"(a));
}
__device__ __forceinline__ void mma16816(float* c, const uint32_t* a, const uint32_t* b){
    asm volatile("mma.sync.aligned.m16n8k16.row.col.f32.bf16.bf16.f32 "
        "{%0,%1,%2,%3}, {%4,%5,%6,%7}, {%8,%9}, {%0,%1,%2,%3};"
        : "+f"(c[0]),"+f"(c[1]),"+f"(c[2]),"+f"(c[3])
        : "r"(a[0]),"r"(a[1]),"r"(a[2]),"r"(a[3]), "r"(b[0]),"r"(b[1]));
}
__device__ __forceinline__ float gelu_f(float x){ return 0.5f*x*(1.f+erff(x*0.70710678118654752f)); }
__device__ __forceinline__ void split2(float v, bf16& hi, bf16& lo){
    hi = __float2bfloat16_rn(v);
    lo = __float2bfloat16_rn(v - __bfloat162float(hi));
}

// ---------------- bf16 mma GEMM core ----------------
// C[128, BN] = A[128,K] x Bt[BN,K]^T ; BK=64, 3-stage cp.async, 8 warps (4x2)
// EPI: 1 fp32 out *scale; 3 fp32 RMW +bias (residual); 4 gelu(+bias) -> split bf16 (seg); 5 fp32 out +bias
template<int BN, int EPI>
__device__ __forceinline__ void mma_core(
    const bf16* a0,const bf16* a1,const bf16* a2,const bf16* a3,
    const bf16* b0,const bf16* b1,const bf16* b2,const bf16* b3,
    void* Cv, int ldc, const float* bias, int K, float scale, int seg)
{
    extern __shared__ __align__(128) char dsm[];
    constexpr int STAGE = 16384 + BN*128;
    const uint32_t sb = smem_u32(dsm);
    const int tid = threadIdx.x;
    const int lane = tid & 31, wid = tid >> 5;
    const int wm = wid & 3, wn = wid >> 2;
    const bf16* Ar[4] = {a0,a1,a2,a3};
    const bf16* Br[4] = {b0,b1,b2,b3};
    constexpr int NBR = BN/32;
    constexpr int NT  = BN/16;

    float acc[2][NT][4];
    #pragma unroll
    for (int mt=0;mt<2;mt++)
        #pragma unroll
        for (int nt=0;nt<NT;nt++)
            #pragma unroll
            for (int q=0;q<4;q++) acc[mt][nt][q]=0.f;

    const int r8 = tid>>3, cu = tid&7;
    auto load_stage = [&](int st, int kc){
        uint32_t ua = sb + st*STAGE;
        uint32_t ub = ua + 16384;
        #pragma unroll
        for (int i=0;i<4;i++){
            uint32_t ro = r8 + 32*i;
            cpasync16(ua + ro*128 + ((cu ^ (ro&7))<<4), Ar[i] + kc*64);
        }
        #pragma unroll
        for (int i=0;i<NBR;i++){
            uint32_t ro = r8 + 32*i;
            cpasync16(ub + ro*128 + ((cu ^ (ro&7))<<4), Br[i] + kc*64);
        }
    };
    auto compute_stage = [&](int st){
        uint32_t ua = sb + st*STAGE;
        uint32_t ub = ua + 16384;
        #pragma unroll
        for (int ks=0;ks<4;ks++){
            uint32_t a[2][4];
            #pragma unroll
            for (int mt=0;mt<2;mt++){
                uint32_t r = wm*32 + mt*16 + (lane&15);
                uint32_t c = ks*2 + (lane>>4);
                ldm4(a[mt], ua + r*128 + ((c ^ (r&7))<<4));
            }
            uint32_t b[NT][2];
            #pragma unroll
            for (int p=0;p<NT/2;p++){
                uint32_t r = wn*(BN/2) + p*16 + ((lane>>4)<<3) + (lane&7);
                uint32_t c = ks*2 + ((lane>>3)&1);
                uint32_t t[4];
                ldm4(t, ub + r*128 + ((c ^ (r&7))<<4));
                b[2*p][0]=t[0]; b[2*p][1]=t[1]; b[2*p+1][0]=t[2]; b[2*p+1][1]=t[3];
            }
            #pragma unroll
            for (int mt=0;mt<2;mt++)
                #pragma unroll
                for (int nt=0;nt<NT;nt++)
                    mma16816(acc[mt][nt], a[mt], b[nt]);
        }
    };

    const int nk = K >> 6;
    load_stage(0,0); CP_COMMIT();
    if (nk>1){ load_stage(1,1); CP_COMMIT(); }
    for (int k0=0;k0<nk;k0++){
        if (k0+2<=nk) CP_WAIT1(); else CP_WAIT0();
        __syncthreads();
        if (k0+2<nk){ load_stage((k0+2)%3, k0+2); CP_COMMIT(); }
        compute_stage(k0%3);
    }

    #pragma unroll
    for (int mt=0;mt<2;mt++){
        #pragma unroll
        for (int nt=0;nt<NT;nt++){
            int m0 = wm*32 + mt*16 + (lane>>2);
            int n  = wn*(BN/2) + nt*8 + ((lane&3)<<1);
            #pragma unroll
            for (int h=0;h<2;h++){
                int m = m0 + h*8;
                float v0 = acc[mt][nt][2*h], v1 = acc[mt][nt][2*h+1];
                if (EPI==1){
                    *(float2*)((float*)Cv + (size_t)m*ldc + n) = make_float2(v0*scale, v1*scale);
                } else if (EPI==3){
                    float2 bb = *(const float2*)(bias + n);
                    float* p = (float*)Cv + (size_t)m*ldc + n;
                    float2 o = *(float2*)p;
                    *(float2*)p = make_float2(o.x+v0+bb.x, o.y+v1+bb.y);
                } else if (EPI==4){
                    float2 bb = *(const float2*)(bias + n);
                    float g0 = gelu_f(v0+bb.x), g1 = gelu_f(v1+bb.y);
                    bf16 h0,l0,h1,l1; split2(g0,h0,l0); split2(g1,h1,l1);
                    bf16* p = (bf16*)Cv + (size_t)m*ldc + n;
                    *(bf162*)p            = bf162(h0,h1);
                    *(bf162*)(p + seg)    = bf162(l0,l1);
                    *(bf162*)(p + 2*seg)  = bf162(h0,h1);
                } else if (EPI==5){
                    float2 bb = *(const float2*)(bias + n);
                    *(float2*)((float*)Cv + (size_t)m*ldc + n) = make_float2(v0+bb.x, v1+bb.y);
                }
            }
        }
    }
}

// ---------------- GEMM wrappers ----------------
template<int EPI>
__global__ void __launch_bounds__(256,1) k_mma(
    const bf16* __restrict__ A, int lda,
    const bf16* __restrict__ Bt, int ldb,
    float* __restrict__ C, int ldc,
    const float* __restrict__ bias, int K, float scale)
{
    const int t=threadIdx.x, r=t>>3, co=(t&7)*8;
    const bf16* a[4]; const bf16* b[4];
    #pragma unroll
    for (int i=0;i<4;i++){
        a[i] = A  + (size_t)(blockIdx.y*128 + r + 32*i)*lda + co;
        b[i] = Bt + (size_t)(blockIdx.x*128 + r + 32*i)*ldb + co;
    }
    float* Ct = C + (size_t)blockIdx.y*128*ldc + blockIdx.x*128;
    const float* bi = bias ? bias + blockIdx.x*128 : (const float*)0;
    mma_core<128,EPI>(a[0],a[1],a[2],a[3],b[0],b[1],b[2],b[3],Ct,ldc,bi,K,scale,0);
}

__global__ void __launch_bounds__(256,1) k_scores_mma(){
    const int bh=blockIdx.z;
    const bf16* Q = g_qh + (size_t)bh*NSEQ*3*DH;
    const bf16* Kp= g_kh + (size_t)bh*NSEQ*3*DH;
    const int t=threadIdx.x, r=t>>3, co=(t&7)*8;
    const bf16* a[4]; const bf16* b[4];
    #pragma unroll
    for (int i=0;i<4;i++){
        a[i] = Q  + (size_t)(blockIdx.y*128 + r + 32*i)*(3*DH) + co;
        b[i] = Kp + (size_t)(blockIdx.x*128 + r + 32*i)*(3*DH) + co;
    }
    float* Ct = g_scores + (size_t)bh*NSEQ*NSEQ + (size_t)blockIdx.y*128*NSEQ + blockIdx.x*128;
    mma_core<128,1>(a[0],a[1],a[2],a[3],b[0],b[1],b[2],b[3],Ct,NSEQ,(const float*)0,3*DH,0.125f,0);
}

__global__ void __launch_bounds__(256,1) k_av_mma(){
    const int bh=blockIdx.z, b=bh>>3, h=bh&7;
    const bf16* A  = g_probsh + (size_t)bh*NSEQ*3*NSEQ;
    const bf16* Bt = g_vth + (size_t)bh*DH*3*NSEQ;
    const int t=threadIdx.x, r=t>>3, co=(t&7)*8;
    const bf16* a[4]; const bf16* bb[2];
    #pragma unroll
    for (int i=0;i<4;i++)
        a[i] = A + (size_t)(blockIdx.y*128 + r + 32*i)*(3*NSEQ) + co;
    #pragma unroll
    for (int i=0;i<2;i++)
        bb[i] = Bt + (size_t)(r + 32*i)*(3*NSEQ) + co;
    float* Ct = g_attn + (size_t)b*NSEQ*DM + (size_t)blockIdx.y*128*DM + h*DH;
    mma_core<64,1>(a[0],a[1],a[2],a[3],bb[0],bb[1],(const bf16*)0,(const bf16*)0,Ct,DM,(const float*)0,3*NSEQ,1.f,0);
}

template<int EPI, int GATHER>
__global__ void __launch_bounds__(256,1) k_moe_mma(
    const bf16* __restrict__ Abase, int lda,
    const bf16* __restrict__ BtAll, int ldb,
    void* __restrict__ Cbase, int ldc,
    const float* __restrict__ biasAll, int K, int N, int seg)
{
    const int e = g_map[blockIdx.y];
    if (e < 0) return;
    const bf16* Bt = BtAll + (size_t)e*N*K;
    const float* bias = biasAll + (size_t)e*N + blockIdx.x*128;
    const int t=threadIdx.x, r=t>>3, co=(t&7)*8;
    const bf16* a[4]; const bf16* b[4];
    if (GATHER){
        const int lim = g_off[e] + g_cnt[e];
        #pragma unroll
        for (int i=0;i<4;i++){
            int s = blockIdx.y*128 + r + 32*i;
            int tok = (s < lim) ? g_tok[s] : 0;
            a[i] = Abase + (size_t)tok*lda + co;
        }
    } else {
        #pragma unroll
        for (int i=0;i<4;i++)
            a[i] = Abase + (size_t)(blockIdx.y*128 + r + 32*i)*lda + co;
    }
    #pragma unroll
    for (int i=0;i<4;i++)
        b[i] = Bt + (size_t)(blockIdx.x*128 + r + 32*i)*ldb + co;
    char* Ct;
    if (EPI==4) Ct = (char*)Cbase + ((size_t)blockIdx.y*128*ldc + blockIdx.x*128)*2;
    else        Ct = (char*)Cbase + ((size_t)blockIdx.y*128*ldc + blockIdx.x*128)*4;
    mma_core<128,EPI>(a[0],a[1],a[2],a[3],b[0],b[1],b[2],b[3],(void*)Ct,ldc,bias,K,1.f,seg);
}

// ---------------- conversions / transposes ----------------
// weight [R][C] fp32 -> B-split [C][3R] bf16  (hi | hi | lo)
__global__ void k_trw3(const float* __restrict__ in, bf16* __restrict__ out, int R, int C){
    __shared__ float tile[32][33];
    const float* I = in + (size_t)blockIdx.z*R*C;
    bf16* O = out + (size_t)blockIdx.z*R*C*3;
    int r0=blockIdx.y*32, c0=blockIdx.x*32;
    int x=threadIdx.x, y=threadIdx.y;
    #pragma unroll
    for (int i=0;i<4;i++) tile[y+8*i][x] = I[(size_t)(r0+y+8*i)*C + c0+x];
    __syncthreads();
    #pragma unroll
    for (int i=0;i<4;i++){
        float v = tile[x][y+8*i];
        bf16 hi, lo; split2(v, hi, lo);
        bf16* p = O + (size_t)(c0+y+8*i)*3*R + r0+x;
        p[0] = hi; p[R] = hi; p[2*R] = lo;
    }
}

// qkv fp32 -> split Q (A-form) and K (B-form), per head
__global__ void k_cvt_qk(){
    int gid = blockIdx.x*blockDim.x + threadIdx.x;   // TTOK*512
    int t = gid >> 9, c = gid & 511;
    int h = c >> 6, d = c & 63;
    int b = t >> 10, n = t & 1023;
    size_t base = ((size_t)(b*8+h)*NSEQ + n)*(3*DH);
    float qv = g_qkv[(size_t)t*QKVN + c];
    float kv = g_qkv[(size_t)t*QKVN + 512 + c];
    bf16 qh,ql,kh,kl; split2(qv,qh,ql); split2(kv,kh,kl);
    g_qh[base + d] = qh; g_qh[base + 64 + d] = ql; g_qh[base + 128 + d] = qh;
    g_kh[base + d] = kh; g_kh[base + 64 + d] = kh; g_kh[base + 128 + d] = kl;
}

// V slice of qkv fp32 -> transposed B-split [bh][64][3*1024]
__global__ void k_trv3(){
    __shared__ float tile[32][33];
    int bh=blockIdx.z, b=bh>>3, h=bh&7;
    const float* I = g_qkv + (size_t)b*NSEQ*QKVN + 1024 + h*DH;
    bf16* O = g_vth + (size_t)bh*DH*3*NSEQ;
    int n0=blockIdx.y*32, d0=blockIdx.x*32;
    int x=threadIdx.x, y=threadIdx.y;
    #pragma unroll
    for (int i=0;i<4;i++) tile[y+8*i][x] = I[(size_t)(n0+y+8*i)*QKVN + d0+x];
    __syncthreads();
    #pragma unroll
    for (int i=0;i<4;i++){
        float v = tile[x][y+8*i];
        bf16 hi, lo; split2(v, hi, lo);
        bf16* p = O + (size_t)(d0+y+8*i)*3*NSEQ + n0+x;
        p[0] = hi; p[NSEQ] = hi; p[2*NSEQ] = lo;
    }
}

// attn fp32 [t][512] -> A-split [t][1536]
__global__ void k_cvt_attn(){
    int t = blockIdx.x, i = threadIdx.x;     // 128 thr x 4
    const float4 v = ((const float4*)(g_attn + (size_t)t*DM))[i];
    bf16* p = g_attnsp + (size_t)t*3*DM + 4*i;
    bf16 h0,l0,h1,l1,h2,l2,h3,l3;
    split2(v.x,h0,l0); split2(v.y,h1,l1); split2(v.z,h2,l2); split2(v.w,h3,l3);
    *(bf162*)(p)        = bf162(h0,h1); *(bf162*)(p+2)        = bf162(h2,h3);
    *(bf162*)(p+DM)     = bf162(l0,l1); *(bf162*)(p+DM+2)     = bf162(l2,l3);
    *(bf162*)(p+2*DM)   = bf162(h0,h1); *(bf162*)(p+2*DM+2)   = bf162(h2,h3);
}

// ---------------- elementwise / routing ----------------
__global__ void k_copy4(const float4* __restrict__ in, float4* __restrict__ out, int n4){
    int i = blockIdx.x*blockDim.x + threadIdx.x;
    if (i < n4) out[i] = in[i];
}

// LN -> A-split bf16 out (and optional fp32 out)
template<int F32OUT>
__global__ void k_ln_h(const float* __restrict__ in, bf16* __restrict__ outh,
                       float* __restrict__ outf,
                       const float* __restrict__ w, const float* __restrict__ b){
    int t = blockIdx.x, i = threadIdx.x;
    float4 v = ((const float4*)(in + (size_t)t*DM))[i];
    float s  = v.x+v.y+v.z+v.w;
    float ss = v.x*v.x+v.y*v.y+v.z*v.z+v.w*v.w;
    #pragma unroll
    for (int o=16;o;o>>=1){ s += __shfl_xor_sync(0xffffffffu,s,o); ss += __shfl_xor_sync(0xffffffffu,ss,o); }
    __shared__ float sh_s[4], sh_q[4];
    int wid = i>>5, lane = i&31;
    if (lane==0){ sh_s[wid]=s; sh_q[wid]=ss; }
    __syncthreads();
    s  = sh_s[0]+sh_s[1]+sh_s[2]+sh_s[3];
    ss = sh_q[0]+sh_q[1]+sh_q[2]+sh_q[3];
    float mean = s * (1.0f/DM);
    float var  = ss * (1.0f/DM) - mean*mean;
    float inv  = rsqrtf(var + 1e-5f);
    float4 wv = ((const float4*)w)[i];
    float4 bv = ((const float4*)b)[i];
    float4 o;
    o.x=(v.x-mean)*inv*wv.x+bv.x; o.y=(v.y-mean)*inv*wv.y+bv.y;
    o.z=(v.z-mean)*inv*wv.z+bv.z; o.w=(v.w-mean)*inv*wv.w+bv.w;
    bf16* p = outh + (size_t)t*3*DM + 4*i;
    bf16 h0,l0,h1,l1,h2,l2,h3,l3;
    split2(o.x,h0,l0); split2(o.y,h1,l1); split2(o.z,h2,l2); split2(o.w,h3,l3);
    *(bf162*)(p)      = bf162(h0,h1); *(bf162*)(p+2)      = bf162(h2,h3);
    *(bf162*)(p+DM)   = bf162(l0,l1); *(bf162*)(p+DM+2)   = bf162(l2,l3);
    *(bf162*)(p+2*DM) = bf162(h0,h1); *(bf162*)(p+2*DM+2) = bf162(h2,h3);
    if (F32OUT) ((float4*)(outf + (size_t)t*DM))[i] = o;
}

__global__ void k_ln_f(const float* __restrict__ in, float* __restrict__ out,
                       const float* __restrict__ w, const float* __restrict__ b){
    int t = blockIdx.x, i = threadIdx.x;
    float4 v = ((const float4*)(in + (size_t)t*DM))[i];
    float s  = v.x+v.y+v.z+v.w;
    float ss = v.x*v.x+v.y*v.y+v.z*v.z+v.w*v.w;
    #pragma unroll
    for (int o=16;o;o>>=1){ s += __shfl_xor_sync(0xffffffffu,s,o); ss += __shfl_xor_sync(0xffffffffu,ss,o); }
    __shared__ float sh_s[4], sh_q[4];
    int wid = i>>5, lane = i&31;
    if (lane==0){ sh_s[wid]=s; sh_q[wid]=ss; }
    __syncthreads();
    s  = sh_s[0]+sh_s[1]+sh_s[2]+sh_s[3];
    ss = sh_q[0]+sh_q[1]+sh_q[2]+sh_q[3];
    float mean = s * (1.0f/DM);
    float var  = ss * (1.0f/DM) - mean*mean;
    float inv  = rsqrtf(var + 1e-5f);
    float4 wv = ((const float4*)w)[i];
    float4 bv = ((const float4*)b)[i];
    float4 o;
    o.x=(v.x-mean)*inv*wv.x+bv.x; o.y=(v.y-mean)*inv*wv.y+bv.y;
    o.z=(v.z-mean)*inv*wv.z+bv.z; o.w=(v.w-mean)*inv*wv.w+bv.w;
    ((float4*)(out + (size_t)t*DM))[i] = o;
}

__global__ void k_softmax(){
    const float* row = g_scores + (size_t)blockIdx.x*NSEQ;
    bf16* orow = g_probsh + (size_t)blockIdx.x*3*NSEQ;
    int i = threadIdx.x;
    float4 v = ((const float4*)row)[i];
    float m = fmaxf(fmaxf(v.x,v.y), fmaxf(v.z,v.w));
    #pragma unroll
    for (int o=16;o;o>>=1) m = fmaxf(m, __shfl_xor_sync(0xffffffffu,m,o));
    __shared__ float sh[8];
    int wid = i>>5, lane = i&31;
    if (lane==0) sh[wid]=m;
    __syncthreads();
    float bm = sh[0];
    #pragma unroll
    for (int w=1;w<8;w++) bm = fmaxf(bm, sh[w]);
    v.x = __expf(v.x-bm); v.y = __expf(v.y-bm); v.z = __expf(v.z-bm); v.w = __expf(v.w-bm);
    float s = v.x+v.y+v.z+v.w;
    #pragma unroll
    for (int o=16;o;o>>=1) s += __shfl_xor_sync(0xffffffffu,s,o);
    __syncthreads();
    if (lane==0) sh[wid]=s;
    __syncthreads();
    float bs = sh[0]+sh[1]+sh[2]+sh[3]+sh[4]+sh[5]+sh[6]+sh[7];
    float inv = 1.0f/bs;
    v.x*=inv; v.y*=inv; v.z*=inv; v.w*=inv;
    bf16 h0,l0,h1,l1,h2,l2,h3,l3;
    split2(v.x,h0,l0); split2(v.y,h1,l1); split2(v.z,h2,l2); split2(v.w,h3,l3);
    bf16* p = orow + 4*i;
    *(bf162*)(p)        = bf162(h0,h1); *(bf162*)(p+2)        = bf162(h2,h3);
    *(bf162*)(p+NSEQ)   = bf162(l0,l1); *(bf162*)(p+NSEQ+2)   = bf162(l2,l3);
    *(bf162*)(p+2*NSEQ) = bf162(h0,h1); *(bf162*)(p+2*NSEQ+2) = bf162(h2,h3);
}

__global__ void k_gate(const float* __restrict__ wg){
    int gid = blockIdx.x*blockDim.x + threadIdx.x;
    if (gid >= TTOK*NE) return;
    int t = gid>>3, e = gid&7;
    const float* xr = g_y + (size_t)t*DM;
    float s = 0.f;
    #pragma unroll 8
    for (int k=0;k<DM;k++) s = fmaf(xr[k], wg[k*NE+e], s);
    g_logits[t*NE+e] = s;
}

__global__ void k_zero_cnt(){ if (threadIdx.x < NE) g_cnt[threadIdx.x] = 0; }
__global__ void k_init_tok(){
    int i = blockIdx.x*blockDim.x + threadIdx.x;
    if (i < SLOTMAX) g_tok[i] = 0;
}

__global__ void k_top2(){
    int t = blockIdx.x*blockDim.x + threadIdx.x;
    if (t >= TTOK) return;
    const float* lr = g_logits + t*NE;
    int i0 = 0; float v0 = lr[0];
    #pragma unroll
    for (int e=1;e<NE;e++){ float v = lr[e]; if (v > v0){ v0=v; i0=e; } }
    int i1 = -1; float v1 = -3.4e38f;
    #pragma unroll
    for (int e=0;e<NE;e++){ if (e==i0) continue; float v = lr[e]; if (v > v1){ v1=v; i1=e; } }
    float e1v = expf(v1 - v0);
    float inv = 1.0f/(1.0f + e1v);
    g_e0[t]=i0; g_e1i[t]=i1;
    g_g0[t]=inv; g_g1[t]=e1v*inv;
    atomicAdd(&g_cnt[i0],1);
    atomicAdd(&g_cnt[i1],1);
}

__global__ void k_scan(){
    int off = 0, rb = 0;
    for (int e=0;e<NE;e++){
        g_off[e] = off; g_cur[e] = off;
        int nb = (g_cnt[e] + 127) >> 7;
        for (int i=0;i<nb;i++) g_map[rb++] = e;
        off += nb*128;
    }
    for (; rb<MAXRB; rb++) g_map[rb] = -1;
}

__global__ void k_scatter(){
    int t = blockIdx.x*blockDim.x + threadIdx.x;
    if (t >= TTOK) return;
    int p0 = atomicAdd(&g_cur[g_e0[t]], 1);  g_tok[p0]=t; g_slotA[t]=p0;
    int p1 = atomicAdd(&g_cur[g_e1i[t]], 1); g_tok[p1]=t; g_slotB[t]=p1;
}

__global__ void k_combine(){
    int t = blockIdx.x, i = threadIdx.x;
    float gg0 = g_g0[t], gg1 = g_g1[t];
    float4 a = ((const float4*)(g_y2 + (size_t)g_slotA[t]*DM))[i];
    float4 b = ((const float4*)(g_y2 + (size_t)g_slotB[t]*DM))[i];
    float4* xr = (float4*)(g_x + (size_t)t*DM);
    float4 xv = xr[i];
    xv.x += gg0*a.x + gg1*b.x;
    xv.y += gg0*a.y + gg1*b.y;
    xv.z += gg0*a.z + gg1*b.z;
    xv.w += gg0*a.w + gg1*b.w;
    xr[i] = xv;
}

// ---------------- host orchestration ----------------
#define SMEM128 (3*(16384 + 128*128))   /* 98304 */
#define SMEM64  (3*(16384 +  64*128))   /* 73728 */

extern "C" void kernel_launch(void* const* d_in, const int* in_sizes, int n_in,
                              void* d_out, int out_size){
    (void)in_sizes; (void)n_in; (void)out_size;
    const float* x    = (const float*)d_in[0];
    const float* ln1w = (const float*)d_in[1];
    const float* ln1b = (const float*)d_in[2];
    const float* qkvw = (const float*)d_in[3];
    const float* outw = (const float*)d_in[4];
    const float* outb = (const float*)d_in[5];
    const float* ln2w = (const float*)d_in[6];
    const float* ln2b = (const float*)d_in[7];
    const float* wg   = (const float*)d_in[8];
    const float* ew1  = (const float*)d_in[9];
    const float* eb1  = (const float*)d_in[10];
    const float* ew2  = (const float*)d_in[11];
    const float* eb2  = (const float*)d_in[12];
    const float* flnw = (const float*)d_in[13];
    const float* flnb = (const float*)d_in[14];
    float* out = (float*)d_out;

    float *px, *py, *pq, *py2;
    bf16 *pyh, *phh, *pattnsp, *pqkvT, *poutT, *pe1T, *pe2T;
    cudaGetSymbolAddress((void**)&px,   g_x);
    cudaGetSymbolAddress((void**)&py,   g_y);
    cudaGetSymbolAddress((void**)&pq,   g_qkv);
    cudaGetSymbolAddress((void**)&py2,  g_y2);
    cudaGetSymbolAddress((void**)&pyh,  g_yh);
    cudaGetSymbolAddress((void**)&phh,  g_hh);
    cudaGetSymbolAddress((void**)&pattnsp, g_attnsp);
    cudaGetSymbolAddress((void**)&pqkvT,g_qkvwT);
    cudaGetSymbolAddress((void**)&poutT,g_outwT);
    cudaGetSymbolAddress((void**)&pe1T, g_e1T);
    cudaGetSymbolAddress((void**)&pe2T, g_e2T);

    cudaFuncSetAttribute(k_mma<1>, cudaFuncAttributeMaxDynamicSharedMemorySize, SMEM128);
    cudaFuncSetAttribute(k_mma<3>, cudaFuncAttributeMaxDynamicSharedMemorySize, SMEM128);
    cudaFuncSetAttribute(k_scores_mma, cudaFuncAttributeMaxDynamicSharedMemorySize, SMEM128);
    cudaFuncSetAttribute(k_av_mma, cudaFuncAttributeMaxDynamicSharedMemorySize, SMEM64);
    cudaFuncSetAttribute(k_moe_mma<4,1>, cudaFuncAttributeMaxDynamicSharedMemorySize, SMEM128);
    cudaFuncSetAttribute(k_moe_mma<5,0>, cudaFuncAttributeMaxDynamicSharedMemorySize, SMEM128);

    {   int n4 = TTOK*DM/4;
        k_copy4<<<(n4+255)/256, 256>>>((const float4*)x, (float4*)px, n4); }

    // weight transpose + 3-way bf16 split (B-form: hi|hi|lo along K)
    k_trw3<<<dim3(QKVN/32, DM/32, NL), dim3(32,8)>>>(qkvw, pqkvT, DM, QKVN);
    k_trw3<<<dim3(DM/32,   DM/32, NL), dim3(32,8)>>>(outw, poutT, DM, DM);
    k_trw3<<<dim3(HFF/32,  DM/32, NL*NE), dim3(32,8)>>>(ew1, pe1T, DM, HFF);
    k_trw3<<<dim3(DM/32,  HFF/32, NL*NE), dim3(32,8)>>>(ew2, pe2T, HFF, DM);

    for (int l=0;l<NL;l++){
        // ---- attention ----
        k_ln_h<0><<<TTOK,128>>>(px, pyh, (float*)0, ln1w + l*DM, ln1b + l*DM);
        k_mma<1><<<dim3(QKVN/128, TTOK/128), 256, SMEM128>>>(
            pyh, 3*DM, pqkvT + (size_t)l*QKVN*3*DM, 3*DM, pq, QKVN, (const float*)0, 3*DM, 1.f);
        k_cvt_qk<<<(TTOK*512)/256, 256>>>();
        k_trv3<<<dim3(2, NSEQ/32, 64), dim3(32,8)>>>();
        k_scores_mma<<<dim3(NSEQ/128, NSEQ/128, 64), 256, SMEM128>>>();
        k_softmax<<<64*NSEQ, 256>>>();
        k_av_mma<<<dim3(1, NSEQ/128, 64), 256, SMEM64>>>();
        k_cvt_attn<<<TTOK,128>>>();
        k_mma<3><<<dim3(DM/128, TTOK/128), 256, SMEM128>>>(
            pattnsp, 3*DM, poutT + (size_t)l*DM*3*DM, 3*DM, px, DM, outb + l*DM, 3*DM, 1.f);
        // ---- MoE ----
        k_ln_h<1><<<TTOK,128>>>(px, pyh, py, ln2w + l*DM, ln2b + l*DM);
        k_zero_cnt<<<1,32>>>();
        k_init_tok<<<(SLOTMAX+255)/256,256>>>();
        k_gate<<<(TTOK*NE)/256, 256>>>(wg + (size_t)l*DM*NE);
        k_top2<<<TTOK/256, 256>>>();
        k_scan<<<1,1>>>();
        k_scatter<<<TTOK/256, 256>>>();
        k_moe_mma<4,1><<<dim3(HFF/128, MAXRB), 256, SMEM128>>>(
            pyh, 3*DM, pe1T + (size_t)l*NE*HFF*3*DM, 3*DM, phh, 3*HFF,
            eb1 + (size_t)l*NE*HFF, 3*DM, HFF, HFF);
        k_moe_mma<5,0><<<dim3(DM/128, MAXRB), 256, SMEM128>>>(
            phh, 3*HFF, pe2T + (size_t)l*NE*DM*3*HFF, 3*HFF, py2, DM,
            eb2 + (size_t)l*NE*DM, 3*HFF, DM, 0);
        k_combine<<<TTOK,128>>>();
    }

    k_ln_f<<<TTOK,128>>>(px, out, flnw, flnb);
}

// round 5
// speedup vs baseline: 2.4322x; 1.1707x over previous
#include <cuda_runtime.h>
#include <cuda_bf16.h>
#include <math.h>
#include <stdint.h>

#define TTOK 8192
#define DM   512
#define QKVN 1536
#define HFF  2048
#define NE   8
#define NSEQ 1024
#define DH   64
#define NL   4
#define SLOTMAX (2*TTOK + NE*128)   /* 17408 */
#define MAXRB   (SLOTMAX/128)       /* 136   */

typedef __nv_bfloat16  bf16;
typedef __nv_bfloat162 bf162;

// ---------------- static device scratch ----------------
__device__ __align__(128) float g_x[TTOK*DM];
__device__ __align__(128) float g_y[TTOK*DM];
__device__ __align__(128) float g_qkv[(size_t)TTOK*QKVN];
__device__ __align__(128) float g_scores[(size_t)64*NSEQ*NSEQ];
__device__ __align__(128) float g_y2[(size_t)SLOTMAX*DM];
__device__ __align__(128) float g_logits[TTOK*NE];
__device__ __align__(128) bf16  g_yh[(size_t)TTOK*3*DM];            // A-split LN out
__device__ __align__(128) bf16  g_qh[(size_t)64*NSEQ*3*DH];         // A-split Q
__device__ __align__(128) bf16  g_kh[(size_t)64*NSEQ*3*DH];         // B-split K
__device__ __align__(128) bf16  g_vth[(size_t)64*DH*3*NSEQ];        // B-split V^T
__device__ __align__(128) bf16  g_probsh[(size_t)64*NSEQ*3*NSEQ];   // A-split probs
__device__ __align__(128) bf16  g_attnsp[(size_t)TTOK*3*DM];        // A-split attn out
__device__ __align__(128) bf16  g_hh[(size_t)SLOTMAX*3*HFF];        // A-split moe hidden
__device__ __align__(128) bf16  g_qkvwT[(size_t)NL*QKVN*3*DM];      // B-split weights
__device__ __align__(128) bf16  g_outwT[(size_t)NL*DM*3*DM];
__device__ __align__(128) bf16  g_e1T[(size_t)NL*NE*HFF*3*DM];
__device__ __align__(128) bf16  g_e2T[(size_t)NL*NE*DM*3*HFF];
__device__ int   g_e0[TTOK], g_e1i[TTOK];
__device__ float g_g0[TTOK], g_g1[TTOK];
__device__ int   g_cnt[NE], g_off[NE], g_cur[NE];
__device__ int   g_map[MAXRB];
__device__ int   g_tok[SLOTMAX];
__device__ int   g_slotA[TTOK], g_slotB[TTOK];

// ---------------- low-level helpers ----------------
__device__ __forceinline__ uint32_t smem_u32(const void* p){
    uint32_t a; asm("{ .reg .u64 t; cvta.to.shared.u64 t, %1; cvt.u32.u64 %0, t; }":"=r"(a):"l"(p)); return a;
}
__device__ __forceinline__ void cpasync16(uint32_t dst, const void* src){
    asm volatile("cp.async.cg.shared.global [%0], [%1], 16;" :: "r"(dst), "l"(src));
}
#define CP_COMMIT() asm volatile("cp.async.commit_group;" ::: "memory")
#define CP_WAIT1()  asm volatile("cp.async.wait_group 1;" ::: "memory")
#define CP_WAIT0()  asm volatile("cp.async.wait_group 0;" ::: "memory")
__device__ __forceinline__ void ldm4(uint32_t* r, uint32_t a){
    asm volatile("ldmatrix.sync.aligned.m8n8.x4.shared.b16 {%0,%1,%2,%3}, [%4];"
        : "=r"(r[0]),"=r"(r[1]),"=r"(r[2]),"=r"(r[3]) : "r"(a));
}
__device__ __forceinline__ void mma16816(float* c, const uint32_t* a, const uint32_t* b){
    asm volatile("mma.sync.aligned.m16n8k16.row.col.f32.bf16.bf16.f32 "
        "{%0,%1,%2,%3}, {%4,%5,%6,%7}, {%8,%9}, {%0,%1,%2,%3};"
        : "+f"(c[0]),"+f"(c[1]),"+f"(c[2]),"+f"(c[3])
        : "r"(a[0]),"r"(a[1]),"r"(a[2]),"r"(a[3]), "r"(b[0]),"r"(b[1]));
}
__device__ __forceinline__ float gelu_f(float x){ return 0.5f*x*(1.f+erff(x*0.70710678118654752f)); }
__device__ __forceinline__ void split2(float v, bf16& hi, bf16& lo){
    hi = __float2bfloat16_rn(v);
    lo = __float2bfloat16_rn(v - __bfloat162float(hi));
}

// ---------------- bf16 mma GEMM core (2-stage cp.async, occ 2) ----------------
// C[128, BN] = A[128,K] x Bt[BN,K]^T ; BK=64, 8 warps (4x2)
// EPI: 1 fp32 out *scale; 3 fp32 RMW +bias (residual); 4 gelu(+bias)->split bf16 (seg);
//      5 fp32 out +bias; 6 split bf16 (seg), no bias
template<int BN, int EPI>
__device__ __forceinline__ void mma_core(
    const bf16* a0,const bf16* a1,const bf16* a2,const bf16* a3,
    const bf16* b0,const bf16* b1,const bf16* b2,const bf16* b3,
    void* Cv, int ldc, const float* bias, int K, float scale, int seg)
{
    extern __shared__ __align__(128) char dsm[];
    constexpr int STAGE = 16384 + BN*128;
    const uint32_t sb = smem_u32(dsm);
    const int tid = threadIdx.x;
    const int lane = tid & 31, wid = tid >> 5;
    const int wm = wid & 3, wn = wid >> 2;
    const bf16* Ar[4] = {a0,a1,a2,a3};
    const bf16* Br[4] = {b0,b1,b2,b3};
    constexpr int NBR = BN/32;
    constexpr int NT  = BN/16;

    float acc[2][NT][4];
    #pragma unroll
    for (int mt=0;mt<2;mt++)
        #pragma unroll
        for (int nt=0;nt<NT;nt++)
            #pragma unroll
            for (int q=0;q<4;q++) acc[mt][nt][q]=0.f;

    const int r8 = tid>>3, cu = tid&7;
    auto load_stage = [&](int st, int kc){
        uint32_t ua = sb + st*STAGE;
        uint32_t ub = ua + 16384;
        #pragma unroll
        for (int i=0;i<4;i++){
            uint32_t ro = r8 + 32*i;
            cpasync16(ua + ro*128 + ((cu ^ (ro&7))<<4), Ar[i] + kc*64);
        }
        #pragma unroll
        for (int i=0;i<NBR;i++){
            uint32_t ro = r8 + 32*i;
            cpasync16(ub + ro*128 + ((cu ^ (ro&7))<<4), Br[i] + kc*64);
        }
    };
    auto compute_stage = [&](int st){
        uint32_t ua = sb + st*STAGE;
        uint32_t ub = ua + 16384;
        #pragma unroll
        for (int ks=0;ks<4;ks++){
            uint32_t a[2][4];
            #pragma unroll
            for (int mt=0;mt<2;mt++){
                uint32_t r = wm*32 + mt*16 + (lane&15);
                uint32_t c = ks*2 + (lane>>4);
                ldm4(a[mt], ua + r*128 + ((c ^ (r&7))<<4));
            }
            uint32_t b[NT][2];
            #pragma unroll
            for (int p=0;p<NT/2;p++){
                uint32_t r = wn*(BN/2) + p*16 + ((lane>>4)<<3) + (lane&7);
                uint32_t c = ks*2 + ((lane>>3)&1);
                uint32_t t[4];
                ldm4(t, ub + r*128 + ((c ^ (r&7))<<4));
                b[2*p][0]=t[0]; b[2*p][1]=t[1]; b[2*p+1][0]=t[2]; b[2*p+1][1]=t[3];
            }
            #pragma unroll
            for (int mt=0;mt<2;mt++)
                #pragma unroll
                for (int nt=0;nt<NT;nt++)
                    mma16816(acc[mt][nt], a[mt], b[nt]);
        }
    };

    const int nk = K >> 6;
    load_stage(0,0); CP_COMMIT();
    if (nk>1){ load_stage(1,1); CP_COMMIT(); }
    for (int k0=0;k0<nk;k0++){
        if (k0+1<nk) CP_WAIT1(); else CP_WAIT0();
        __syncthreads();
        compute_stage(k0&1);
        if (k0+2<nk){
            __syncthreads();
            load_stage(k0&1, k0+2); CP_COMMIT();
        }
    }

    #pragma unroll
    for (int mt=0;mt<2;mt++){
        #pragma unroll
        for (int nt=0;nt<NT;nt++){
            int m0 = wm*32 + mt*16 + (lane>>2);
            int n  = wn*(BN/2) + nt*8 + ((lane&3)<<1);
            #pragma unroll
            for (int h=0;h<2;h++){
                int m = m0 + h*8;
                float v0 = acc[mt][nt][2*h], v1 = acc[mt][nt][2*h+1];
                if (EPI==1){
                    *(float2*)((float*)Cv + (size_t)m*ldc + n) = make_float2(v0*scale, v1*scale);
                } else if (EPI==3){
                    float2 bb = *(const float2*)(bias + n);
                    float* p = (float*)Cv + (size_t)m*ldc + n;
                    float2 o = *(float2*)p;
                    *(float2*)p = make_float2(o.x+v0+bb.x, o.y+v1+bb.y);
                } else if (EPI==4){
                    float2 bb = *(const float2*)(bias + n);
                    float g0 = gelu_f(v0+bb.x), g1 = gelu_f(v1+bb.y);
                    bf16 h0,l0,h1,l1; split2(g0,h0,l0); split2(g1,h1,l1);
                    bf16* p = (bf16*)Cv + (size_t)m*ldc + n;
                    *(bf162*)p            = bf162(h0,h1);
                    *(bf162*)(p + seg)    = bf162(l0,l1);
                    *(bf162*)(p + 2*seg)  = bf162(h0,h1);
                } else if (EPI==5){
                    float2 bb = *(const float2*)(bias + n);
                    *(float2*)((float*)Cv + (size_t)m*ldc + n) = make_float2(v0+bb.x, v1+bb.y);
                } else if (EPI==6){
                    bf16 h0,l0,h1,l1; split2(v0,h0,l0); split2(v1,h1,l1);
                    bf16* p = (bf16*)Cv + (size_t)m*ldc + n;
                    *(bf162*)p            = bf162(h0,h1);
                    *(bf162*)(p + seg)    = bf162(l0,l1);
                    *(bf162*)(p + 2*seg)  = bf162(h0,h1);
                }
            }
        }
    }
}

// ---------------- GEMM wrappers ----------------
template<int EPI>
__global__ void __launch_bounds__(256,2) k_mma(
    const bf16* __restrict__ A, int lda,
    const bf16* __restrict__ Bt, int ldb,
    float* __restrict__ C, int ldc,
    const float* __restrict__ bias, int K, float scale)
{
    const int t=threadIdx.x, r=t>>3, co=(t&7)*8;
    const bf16* a[4]; const bf16* b[4];
    #pragma unroll
    for (int i=0;i<4;i++){
        a[i] = A  + (size_t)(blockIdx.y*128 + r + 32*i)*lda + co;
        b[i] = Bt + (size_t)(blockIdx.x*128 + r + 32*i)*ldb + co;
    }
    float* Ct = C + (size_t)blockIdx.y*128*ldc + blockIdx.x*128;
    const float* bi = bias ? bias + blockIdx.x*128 : (const float*)0;
    mma_core<128,EPI>(a[0],a[1],a[2],a[3],b[0],b[1],b[2],b[3],Ct,ldc,bi,K,scale,0);
}

__global__ void __launch_bounds__(256,2) k_scores_mma(){
    const int bh=blockIdx.z;
    const bf16* Q = g_qh + (size_t)bh*NSEQ*3*DH;
    const bf16* Kp= g_kh + (size_t)bh*NSEQ*3*DH;
    const int t=threadIdx.x, r=t>>3, co=(t&7)*8;
    const bf16* a[4]; const bf16* b[4];
    #pragma unroll
    for (int i=0;i<4;i++){
        a[i] = Q  + (size_t)(blockIdx.y*128 + r + 32*i)*(3*DH) + co;
        b[i] = Kp + (size_t)(blockIdx.x*128 + r + 32*i)*(3*DH) + co;
    }
    float* Ct = g_scores + (size_t)bh*NSEQ*NSEQ + (size_t)blockIdx.y*128*NSEQ + blockIdx.x*128;
    mma_core<128,1>(a[0],a[1],a[2],a[3],b[0],b[1],b[2],b[3],Ct,NSEQ,(const float*)0,3*DH,0.125f,0);
}

__global__ void __launch_bounds__(256,2) k_av_mma(){
    const int bh=blockIdx.z, b=bh>>3, h=bh&7;
    const bf16* A  = g_probsh + (size_t)bh*NSEQ*3*NSEQ;
    const bf16* Bt = g_vth + (size_t)bh*DH*3*NSEQ;
    const int t=threadIdx.x, r=t>>3, co=(t&7)*8;
    const bf16* a[4]; const bf16* bb[2];
    #pragma unroll
    for (int i=0;i<4;i++)
        a[i] = A + (size_t)(blockIdx.y*128 + r + 32*i)*(3*NSEQ) + co;
    #pragma unroll
    for (int i=0;i<2;i++)
        bb[i] = Bt + (size_t)(r + 32*i)*(3*NSEQ) + co;
    // write A-split directly: row = b*NSEQ + by*128 + m, cols h*64.. within 3*DM row, seg=DM
    bf16* Ct = g_attnsp + (size_t)(b*NSEQ + blockIdx.y*128)*(3*DM) + h*DH;
    mma_core<64,6>(a[0],a[1],a[2],a[3],bb[0],bb[1],(const bf16*)0,(const bf16*)0,Ct,3*DM,(const float*)0,3*NSEQ,1.f,DM);
}

template<int EPI, int GATHER>
__global__ void __launch_bounds__(256,2) k_moe_mma(
    const bf16* __restrict__ Abase, int lda,
    const bf16* __restrict__ BtAll, int ldb,
    void* __restrict__ Cbase, int ldc,
    const float* __restrict__ biasAll, int K, int N, int seg)
{
    const int e = g_map[blockIdx.y];
    if (e < 0) return;
    const bf16* Bt = BtAll + (size_t)e*N*K;
    const float* bias = biasAll + (size_t)e*N + blockIdx.x*128;
    const int t=threadIdx.x, r=t>>3, co=(t&7)*8;
    const bf16* a[4]; const bf16* b[4];
    if (GATHER){
        const int lim = g_off[e] + g_cnt[e];
        #pragma unroll
        for (int i=0;i<4;i++){
            int s = blockIdx.y*128 + r + 32*i;
            int tok = (s < lim) ? g_tok[s] : 0;
            a[i] = Abase + (size_t)tok*lda + co;
        }
    } else {
        #pragma unroll
        for (int i=0;i<4;i++)
            a[i] = Abase + (size_t)(blockIdx.y*128 + r + 32*i)*lda + co;
    }
    #pragma unroll
    for (int i=0;i<4;i++)
        b[i] = Bt + (size_t)(blockIdx.x*128 + r + 32*i)*ldb + co;
    char* Ct;
    if (EPI==4) Ct = (char*)Cbase + ((size_t)blockIdx.y*128*ldc + blockIdx.x*128)*2;
    else        Ct = (char*)Cbase + ((size_t)blockIdx.y*128*ldc + blockIdx.x*128)*4;
    mma_core<128,EPI>(a[0],a[1],a[2],a[3],b[0],b[1],b[2],b[3],(void*)Ct,ldc,bias,K,1.f,seg);
}

// ---------------- conversions / transposes ----------------
// weight [R][C] fp32 -> B-split [C][3R] bf16  (hi | hi | lo)
__global__ void k_trw3(const float* __restrict__ in, bf16* __restrict__ out, int R, int C){
    __shared__ float tile[32][33];
    const float* I = in + (size_t)blockIdx.z*R*C;
    bf16* O = out + (size_t)blockIdx.z*R*C*3;
    int r0=blockIdx.y*32, c0=blockIdx.x*32;
    int x=threadIdx.x, y=threadIdx.y;
    #pragma unroll
    for (int i=0;i<4;i++) tile[y+8*i][x] = I[(size_t)(r0+y+8*i)*C + c0+x];
    __syncthreads();
    #pragma unroll
    for (int i=0;i<4;i++){
        float v = tile[x][y+8*i];
        bf16 hi, lo; split2(v, hi, lo);
        bf16* p = O + (size_t)(c0+y+8*i)*3*R + r0+x;
        p[0] = hi; p[R] = hi; p[2*R] = lo;
    }
}

// qkv fp32 -> split Q (A-form) and K (B-form), per head
__global__ void k_cvt_qk(){
    int gid = blockIdx.x*blockDim.x + threadIdx.x;   // TTOK*512
    int t = gid >> 9, c = gid & 511;
    int h = c >> 6, d = c & 63;
    int b = t >> 10, n = t & 1023;
    size_t base = ((size_t)(b*8+h)*NSEQ + n)*(3*DH);
    float qv = g_qkv[(size_t)t*QKVN + c];
    float kv = g_qkv[(size_t)t*QKVN + 512 + c];
    bf16 qh,ql,kh,kl; split2(qv,qh,ql); split2(kv,kh,kl);
    g_qh[base + d] = qh; g_qh[base + 64 + d] = ql; g_qh[base + 128 + d] = qh;
    g_kh[base + d] = kh; g_kh[base + 64 + d] = kh; g_kh[base + 128 + d] = kl;
}

// V slice of qkv fp32 -> transposed B-split [bh][64][3*1024]
__global__ void k_trv3(){
    __shared__ float tile[32][33];
    int bh=blockIdx.z, b=bh>>3, h=bh&7;
    const float* I = g_qkv + (size_t)b*NSEQ*QKVN + 1024 + h*DH;
    bf16* O = g_vth + (size_t)bh*DH*3*NSEQ;
    int n0=blockIdx.y*32, d0=blockIdx.x*32;
    int x=threadIdx.x, y=threadIdx.y;
    #pragma unroll
    for (int i=0;i<4;i++) tile[y+8*i][x] = I[(size_t)(n0+y+8*i)*QKVN + d0+x];
    __syncthreads();
    #pragma unroll
    for (int i=0;i<4;i++){
        float v = tile[x][y+8*i];
        bf16 hi, lo; split2(v, hi, lo);
        bf16* p = O + (size_t)(d0+y+8*i)*3*NSEQ + n0+x;
        p[0] = hi; p[NSEQ] = hi; p[2*NSEQ] = lo;
    }
}

// ---------------- elementwise / routing ----------------
__global__ void k_copy4(const float4* __restrict__ in, float4* __restrict__ out, int n4){
    int i = blockIdx.x*blockDim.x + threadIdx.x;
    if (i < n4) out[i] = in[i];
}

// LN -> A-split bf16 out (and optional fp32 out)
template<int F32OUT>
__global__ void k_ln_h(const float* __restrict__ in, bf16* __restrict__ outh,
                       float* __restrict__ outf,
                       const float* __restrict__ w, const float* __restrict__ b){
    int t = blockIdx.x, i = threadIdx.x;
    float4 v = ((const float4*)(in + (size_t)t*DM))[i];
    float s  = v.x+v.y+v.z+v.w;
    float ss = v.x*v.x+v.y*v.y+v.z*v.z+v.w*v.w;
    #pragma unroll
    for (int o=16;o;o>>=1){ s += __shfl_xor_sync(0xffffffffu,s,o); ss += __shfl_xor_sync(0xffffffffu,ss,o); }
    __shared__ float sh_s[4], sh_q[4];
    int wid = i>>5, lane = i&31;
    if (lane==0){ sh_s[wid]=s; sh_q[wid]=ss; }
    __syncthreads();
    s  = sh_s[0]+sh_s[1]+sh_s[2]+sh_s[3];
    ss = sh_q[0]+sh_q[1]+sh_q[2]+sh_q[3];
    float mean = s * (1.0f/DM);
    float var  = ss * (1.0f/DM) - mean*mean;
    float inv  = rsqrtf(var + 1e-5f);
    float4 wv = ((const float4*)w)[i];
    float4 bv = ((const float4*)b)[i];
    float4 o;
    o.x=(v.x-mean)*inv*wv.x+bv.x; o.y=(v.y-mean)*inv*wv.y+bv.y;
    o.z=(v.z-mean)*inv*wv.z+bv.z; o.w=(v.w-mean)*inv*wv.w+bv.w;
    bf16* p = outh + (size_t)t*3*DM + 4*i;
    bf16 h0,l0,h1,l1,h2,l2,h3,l3;
    split2(o.x,h0,l0); split2(o.y,h1,l1); split2(o.z,h2,l2); split2(o.w,h3,l3);
    *(bf162*)(p)      = bf162(h0,h1); *(bf162*)(p+2)      = bf162(h2,h3);
    *(bf162*)(p+DM)   = bf162(l0,l1); *(bf162*)(p+DM+2)   = bf162(l2,l3);
    *(bf162*)(p+2*DM) = bf162(h0,h1); *(bf162*)(p+2*DM+2) = bf162(h2,h3);
    if (F32OUT) ((float4*)(outf + (size_t)t*DM))[i] = o;
}

__global__ void k_ln_f(const float* __restrict__ in, float* __restrict__ out,
                       const float* __restrict__ w, const float* __restrict__ b){
    int t = blockIdx.x, i = threadIdx.x;
    float4 v = ((const float4*)(in + (size_t)t*DM))[i];
    float s  = v.x+v.y+v.z+v.w;
    float ss = v.x*v.x+v.y*v.y+v.z*v.z+v.w*v.w;
    #pragma unroll
    for (int o=16;o;o>>=1){ s += __shfl_xor_sync(0xffffffffu,s,o); ss += __shfl_xor_sync(0xffffffffu,ss,o); }
    __shared__ float sh_s[4], sh_q[4];
    int wid = i>>5, lane = i&31;
    if (lane==0){ sh_s[wid]=s; sh_q[wid]=ss; }
    __syncthreads();
    s  = sh_s[0]+sh_s[1]+sh_s[2]+sh_s[3];
    ss = sh_q[0]+sh_q[1]+sh_q[2]+sh_q[3];
    float mean = s * (1.0f/DM);
    float var  = ss * (1.0f/DM) - mean*mean;
    float inv  = rsqrtf(var + 1e-5f);
    float4 wv = ((const float4*)w)[i];
    float4 bv = ((const float4*)b)[i];
    float4 o;
    o.x=(v.x-mean)*inv*wv.x+bv.x; o.y=(v.y-mean)*inv*wv.y+bv.y;
    o.z=(v.z-mean)*inv*wv.z+bv.z; o.w=(v.w-mean)*inv*wv.w+bv.w;
    ((float4*)(out + (size_t)t*DM))[i] = o;
}

__global__ void k_softmax(){
    const float* row = g_scores + (size_t)blockIdx.x*NSEQ;
    bf16* orow = g_probsh + (size_t)blockIdx.x*3*NSEQ;
    int i = threadIdx.x;
    float4 v = ((const float4*)row)[i];
    float m = fmaxf(fmaxf(v.x,v.y), fmaxf(v.z,v.w));
    #pragma unroll
    for (int o=16;o;o>>=1) m = fmaxf(m, __shfl_xor_sync(0xffffffffu,m,o));
    __shared__ float sh[8];
    int wid = i>>5, lane = i&31;
    if (lane==0) sh[wid]=m;
    __syncthreads();
    float bm = sh[0];
    #pragma unroll
    for (int w=1;w<8;w++) bm = fmaxf(bm, sh[w]);
    v.x = __expf(v.x-bm); v.y = __expf(v.y-bm); v.z = __expf(v.z-bm); v.w = __expf(v.w-bm);
    float s = v.x+v.y+v.z+v.w;
    #pragma unroll
    for (int o=16;o;o>>=1) s += __shfl_xor_sync(0xffffffffu,s,o);
    __syncthreads();
    if (lane==0) sh[wid]=s;
    __syncthreads();
    float bs = sh[0]+sh[1]+sh[2]+sh[3]+sh[4]+sh[5]+sh[6]+sh[7];
    float inv = 1.0f/bs;
    v.x*=inv; v.y*=inv; v.z*=inv; v.w*=inv;
    bf16 h0,l0,h1,l1,h2,l2,h3,l3;
    split2(v.x,h0,l0); split2(v.y,h1,l1); split2(v.z,h2,l2); split2(v.w,h3,l3);
    bf16* p = orow + 4*i;
    *(bf162*)(p)        = bf162(h0,h1); *(bf162*)(p+2)        = bf162(h2,h3);
    *(bf162*)(p+NSEQ)   = bf162(l0,l1); *(bf162*)(p+NSEQ+2)   = bf162(l2,l3);
    *(bf162*)(p+2*NSEQ) = bf162(h0,h1); *(bf162*)(p+2*NSEQ+2) = bf162(h2,h3);
}

__global__ void k_gate(const float* __restrict__ wg){
    int gid = blockIdx.x*blockDim.x + threadIdx.x;
    if (gid >= TTOK*NE) return;
    int t = gid>>3, e = gid&7;
    const float* xr = g_y + (size_t)t*DM;
    float s = 0.f;
    #pragma unroll 8
    for (int k=0;k<DM;k++) s = fmaf(xr[k], wg[k*NE+e], s);
    g_logits[t*NE+e] = s;
}

__global__ void k_zero_cnt(){ if (threadIdx.x < NE) g_cnt[threadIdx.x] = 0; }

__global__ void k_top2(){
    int t = blockIdx.x*blockDim.x + threadIdx.x;
    if (t >= TTOK) return;
    const float* lr = g_logits + t*NE;
    int i0 = 0; float v0 = lr[0];
    #pragma unroll
    for (int e=1;e<NE;e++){ float v = lr[e]; if (v > v0){ v0=v; i0=e; } }
    int i1 = -1; float v1 = -3.4e38f;
    #pragma unroll
    for (int e=0;e<NE;e++){ if (e==i0) continue; float v = lr[e]; if (v > v1){ v1=v; i1=e; } }
    float e1v = expf(v1 - v0);
    float inv = 1.0f/(1.0f + e1v);
    g_e0[t]=i0; g_e1i[t]=i1;
    g_g0[t]=inv; g_g1[t]=e1v*inv;
    atomicAdd(&g_cnt[i0],1);
    atomicAdd(&g_cnt[i1],1);
}

__global__ void k_scan(){
    int off = 0, rb = 0;
    for (int e=0;e<NE;e++){
        g_off[e] = off; g_cur[e] = off;
        int nb = (g_cnt[e] + 127) >> 7;
        for (int i=0;i<nb;i++) g_map[rb++] = e;
        off += nb*128;
    }
    for (; rb<MAXRB; rb++) g_map[rb] = -1;
}

__global__ void k_scatter(){
    int t = blockIdx.x*blockDim.x + threadIdx.x;
    if (t >= TTOK) return;
    int p0 = atomicAdd(&g_cur[g_e0[t]], 1);  g_tok[p0]=t; g_slotA[t]=p0;
    int p1 = atomicAdd(&g_cur[g_e1i[t]], 1); g_tok[p1]=t; g_slotB[t]=p1;
}

__global__ void k_combine(){
    int t = blockIdx.x, i = threadIdx.x;
    float gg0 = g_g0[t], gg1 = g_g1[t];
    float4 a = ((const float4*)(g_y2 + (size_t)g_slotA[t]*DM))[i];
    float4 b = ((const float4*)(g_y2 + (size_t)g_slotB[t]*DM))[i];
    float4* xr = (float4*)(g_x + (size_t)t*DM);
    float4 xv = xr[i];
    xv.x += gg0*a.x + gg1*b.x;
    xv.y += gg0*a.y + gg1*b.y;
    xv.z += gg0*a.z + gg1*b.z;
    xv.w += gg0*a.w + gg1*b.w;
    xr[i] = xv;
}

// ---------------- host orchestration ----------------
#define SMEM128 (2*(16384 + 128*128))   /* 65536 */
#define SMEM64  (2*(16384 +  64*128))   /* 49152 */

extern "C" void kernel_launch(void* const* d_in, const int* in_sizes, int n_in,
                              void* d_out, int out_size){
    (void)in_sizes; (void)n_in; (void)out_size;
    const float* x    = (const float*)d_in[0];
    const float* ln1w = (const float*)d_in[1];
    const float* ln1b = (const float*)d_in[2];
    const float* qkvw = (const float*)d_in[3];
    const float* outw = (const float*)d_in[4];
    const float* outb = (const float*)d_in[5];
    const float* ln2w = (const float*)d_in[6];
    const float* ln2b = (const float*)d_in[7];
    const float* wg   = (const float*)d_in[8];
    const float* ew1  = (const float*)d_in[9];
    const float* eb1  = (const float*)d_in[10];
    const float* ew2  = (const float*)d_in[11];
    const float* eb2  = (const float*)d_in[12];
    const float* flnw = (const float*)d_in[13];
    const float* flnb = (const float*)d_in[14];
    float* out = (float*)d_out;

    float *px, *py, *pq, *py2;
    bf16 *pyh, *phh, *pattnsp, *pqkvT, *poutT, *pe1T, *pe2T;
    cudaGetSymbolAddress((void**)&px,   g_x);
    cudaGetSymbolAddress((void**)&py,   g_y);
    cudaGetSymbolAddress((void**)&pq,   g_qkv);
    cudaGetSymbolAddress((void**)&py2,  g_y2);
    cudaGetSymbolAddress((void**)&pyh,  g_yh);
    cudaGetSymbolAddress((void**)&phh,  g_hh);
    cudaGetSymbolAddress((void**)&pattnsp, g_attnsp);
    cudaGetSymbolAddress((void**)&pqkvT,g_qkvwT);
    cudaGetSymbolAddress((void**)&poutT,g_outwT);
    cudaGetSymbolAddress((void**)&pe1T, g_e1T);
    cudaGetSymbolAddress((void**)&pe2T, g_e2T);

    cudaFuncSetAttribute(k_mma<1>, cudaFuncAttributeMaxDynamicSharedMemorySize, SMEM128);
    cudaFuncSetAttribute(k_mma<3>, cudaFuncAttributeMaxDynamicSharedMemorySize, SMEM128);
    cudaFuncSetAttribute(k_scores_mma, cudaFuncAttributeMaxDynamicSharedMemorySize, SMEM128);
    cudaFuncSetAttribute(k_av_mma, cudaFuncAttributeMaxDynamicSharedMemorySize, SMEM64);
    cudaFuncSetAttribute(k_moe_mma<4,1>, cudaFuncAttributeMaxDynamicSharedMemorySize, SMEM128);
    cudaFuncSetAttribute(k_moe_mma<5,0>, cudaFuncAttributeMaxDynamicSharedMemorySize, SMEM128);

    {   int n4 = TTOK*DM/4;
        k_copy4<<<(n4+255)/256, 256>>>((const float4*)x, (float4*)px, n4); }

    // weight transpose + 3-way bf16 split (B-form: hi|hi|lo along K)
    k_trw3<<<dim3(QKVN/32, DM/32, NL), dim3(32,8)>>>(qkvw, pqkvT, DM, QKVN);
    k_trw3<<<dim3(DM/32,   DM/32, NL), dim3(32,8)>>>(outw, poutT, DM, DM);
    k_trw3<<<dim3(HFF/32,  DM/32, NL*NE), dim3(32,8)>>>(ew1, pe1T, DM, HFF);
    k_trw3<<<dim3(DM/32,  HFF/32, NL*NE), dim3(32,8)>>>(ew2, pe2T, HFF, DM);

    for (int l=0;l<NL;l++){
        // ---- attention ----
        k_ln_h<0><<<TTOK,128>>>(px, pyh, (float*)0, ln1w + l*DM, ln1b + l*DM);
        k_mma<1><<<dim3(QKVN/128, TTOK/128), 256, SMEM128>>>(
            pyh, 3*DM, pqkvT + (size_t)l*QKVN*3*DM, 3*DM, pq, QKVN, (const float*)0, 3*DM, 1.f);
        k_cvt_qk<<<(TTOK*512)/256, 256>>>();
        k_trv3<<<dim3(2, NSEQ/32, 64), dim3(32,8)>>>();
        k_scores_mma<<<dim3(NSEQ/128, NSEQ/128, 64), 256, SMEM128>>>();
        k_softmax<<<64*NSEQ, 256>>>();
        k_av_mma<<<dim3(1, NSEQ/128, 64), 256, SMEM64>>>();
        k_mma<3><<<dim3(DM/128, TTOK/128), 256, SMEM128>>>(
            pattnsp, 3*DM, poutT + (size_t)l*DM*3*DM, 3*DM, px, DM, outb + l*DM, 3*DM, 1.f);
        // ---- MoE ----
        k_ln_h<1><<<TTOK,128>>>(px, pyh, py, ln2w + l*DM, ln2b + l*DM);
        k_zero_cnt<<<1,32>>>();
        k_gate<<<(TTOK*NE)/256, 256>>>(wg + (size_t)l*DM*NE);
        k_top2<<<TTOK/256, 256>>>();
        k_scan<<<1,1>>>();
        k_scatter<<<TTOK/256, 256>>>();
        k_moe_mma<4,1><<<dim3(HFF/128, MAXRB), 256, SMEM128>>>(
            pyh, 3*DM, pe1T + (size_t)l*NE*HFF*3*DM, 3*DM, phh, 3*HFF,
            eb1 + (size_t)l*NE*HFF, 3*DM, HFF, HFF);
        k_moe_mma<5,0><<<dim3(DM/128, MAXRB), 256, SMEM128>>>(
            phh, 3*HFF, pe2T + (size_t)l*NE*DM*3*HFF, 3*HFF, py2, DM,
            eb2 + (size_t)l*NE*DM, 3*HFF, DM, 0);
        k_combine<<<TTOK,128>>>();
    }

    k_ln_f<<<TTOK,128>>>(px, out, flnw, flnb);
}

// round 6
// speedup vs baseline: 2.5621x; 1.0534x over previous
#include <cuda_runtime.h>
#include <cuda_bf16.h>
#include <math.h>
#include <stdint.h>

#define TTOK 8192
#define DM   512
#define QKVN 1536
#define HFF  2048
#define NE   8
#define NSEQ 1024
#define DH   64
#define NL   4
#define SLOTMAX (2*TTOK + NE*128)   /* 17408 */
#define MAXRB   (SLOTMAX/128)       /* 136   */

typedef __nv_bfloat16  bf16;
typedef __nv_bfloat162 bf162;

// ---------------- static device scratch (splits stored 2-wide: [hi|lo]) ----------------
__device__ __align__(128) float g_x[TTOK*DM];
__device__ __align__(128) float g_y[TTOK*DM];
__device__ __align__(128) float g_qkv[(size_t)TTOK*QKVN];
__device__ __align__(128) float g_scores[(size_t)64*NSEQ*NSEQ];
__device__ __align__(128) float g_y2[(size_t)SLOTMAX*DM];
__device__ __align__(128) float g_logits[TTOK*NE];
__device__ __align__(128) bf16  g_yh[(size_t)TTOK*2*DM];
__device__ __align__(128) bf16  g_qh[(size_t)64*NSEQ*2*DH];
__device__ __align__(128) bf16  g_kh[(size_t)64*NSEQ*2*DH];
__device__ __align__(128) bf16  g_vth[(size_t)64*DH*2*NSEQ];
__device__ __align__(128) bf16  g_probsh[(size_t)64*NSEQ*2*NSEQ];
__device__ __align__(128) bf16  g_attnsp[(size_t)TTOK*2*DM];
__device__ __align__(128) bf16  g_hh[(size_t)SLOTMAX*2*HFF];
__device__ __align__(128) bf16  g_qkvwT[(size_t)NL*QKVN*2*DM];
__device__ __align__(128) bf16  g_outwT[(size_t)NL*DM*2*DM];
__device__ __align__(128) bf16  g_e1T[(size_t)NL*NE*HFF*2*DM];
__device__ __align__(128) bf16  g_e2T[(size_t)NL*NE*DM*2*HFF];
__device__ int   g_e0[TTOK], g_e1i[TTOK];
__device__ float g_g0[TTOK], g_g1[TTOK];
__device__ int   g_cnt[NE], g_off[NE], g_cur[NE];
__device__ int   g_map[MAXRB];
__device__ int   g_tok[SLOTMAX];
__device__ int   g_slotA[TTOK], g_slotB[TTOK];

// ---------------- low-level helpers ----------------
__device__ __forceinline__ uint32_t smem_u32(const void* p){
    uint32_t a; asm("{ .reg .u64 t; cvta.to.shared.u64 t, %1; cvt.u32.u64 %0, t; }":"=r"(a):"l"(p)); return a;
}
__device__ __forceinline__ void cpasync16(uint32_t dst, const void* src){
    asm volatile("cp.async.cg.shared.global [%0], [%1], 16;" :: "r"(dst), "l"(src));
}
#define CP_COMMIT() asm volatile("cp.async.commit_group;" ::: "memory")
#define CP_WAIT1()  asm volatile("cp.async.wait_group 1;" ::: "memory")
__device__ __forceinline__ void ldm4(uint32_t* r, uint32_t a){
    asm volatile("ldmatrix.sync.aligned.m8n8.x4.shared.b16 {%0,%1,%2,%3}, [%4];"
        : "=r"(r[0]),"=r"(r[1]),"=r"(r[2]),"=r"(r[3]) : "r"(a));
}
__device__ __forceinline__ void mma16816(float* c, const uint32_t* a, const uint32_t* b){
    asm volatile("mma.sync.aligned.m16n8k16.row.col.f32.bf16.bf16.f32 "
        "{%0,%1,%2,%3}, {%4,%5,%6,%7}, {%8,%9}, {%0,%1,%2,%3};"
        : "+f"(c[0]),"+f"(c[1]),"+f"(c[2]),"+f"(c[3])
        : "r"(a[0]),"r"(a[1]),"r"(a[2]),"r"(a[3]), "r"(b[0]),"r"(b[1]));
}
__device__ __forceinline__ float gelu_f(float x){ return 0.5f*x*(1.f+erff(x*0.70710678118654752f)); }
__device__ __forceinline__ void split2(float v, bf16& hi, bf16& lo){
    hi = __float2bfloat16_rn(v);
    lo = __float2bfloat16_rn(v - __bfloat162float(hi));
}

// ---------------- bf16 mma GEMM core (3-stage cp.async, occ 2) ----------------
// Logical C[128,BN] = A[128, 3*Ko] x Bt[BN, 3*Ko]^T with A segs [hi,lo,hi], B segs [hi,hi,lo],
// but storage is 2-wide [hi|lo]; chunk remap: ca = c<2ma? c : c-2ma ; cb = c<mb? c : c-mb.
// ma = mb = Ko/64 (chunks per segment). K passed = 3*Ko.
// EPI: 1 fp32 out *scale; 3 fp32 RMW +bias (residual); 4 gelu(+bias)->2-seg bf16 (seg);
//      5 fp32 out +bias; 6 2-seg bf16 (seg), no bias
template<int BN, int EPI>
__device__ __forceinline__ void mma_core(
    const bf16* a0,const bf16* a1,const bf16* a2,const bf16* a3,
    const bf16* b0,const bf16* b1,const bf16* b2,const bf16* b3,
    void* Cv, int ldc, const float* bias, int K, float scale, int seg, int ma, int mb)
{
    extern __shared__ __align__(128) char dsm[];
    constexpr int STAGE = 16384 + BN*128;
    const uint32_t sb = smem_u32(dsm);
    const int tid = threadIdx.x;
    const int lane = tid & 31, wid = tid >> 5;
    const int wm = wid & 3, wn = wid >> 2;
    const bf16* Ar[4] = {a0,a1,a2,a3};
    const bf16* Br[4] = {b0,b1,b2,b3};
    constexpr int NBR = BN/32;
    constexpr int NT  = BN/16;

    float acc[2][NT][4];
    #pragma unroll
    for (int mt=0;mt<2;mt++)
        #pragma unroll
        for (int nt=0;nt<NT;nt++)
            #pragma unroll
            for (int q=0;q<4;q++) acc[mt][nt][q]=0.f;

    const int r8 = tid>>3, cu = tid&7;
    auto load_stage = [&](int st, int kc){
        const int ca = (kc < 2*ma) ? kc : kc - 2*ma;
        const int cb = (kc < mb)   ? kc : kc - mb;
        uint32_t ua = sb + st*STAGE;
        uint32_t ub = ua + 16384;
        #pragma unroll
        for (int i=0;i<4;i++){
            uint32_t ro = r8 + 32*i;
            cpasync16(ua + ro*128 + ((cu ^ (ro&7))<<4), Ar[i] + ca*64);
        }
        #pragma unroll
        for (int i=0;i<NBR;i++){
            uint32_t ro = r8 + 32*i;
            cpasync16(ub + ro*128 + ((cu ^ (ro&7))<<4), Br[i] + cb*64);
        }
    };
    auto compute_stage = [&](int st){
        uint32_t ua = sb + st*STAGE;
        uint32_t ub = ua + 16384;
        #pragma unroll
        for (int ks=0;ks<4;ks++){
            uint32_t a[2][4];
            #pragma unroll
            for (int mt=0;mt<2;mt++){
                uint32_t r = wm*32 + mt*16 + (lane&15);
                uint32_t c = ks*2 + (lane>>4);
                ldm4(a[mt], ua + r*128 + ((c ^ (r&7))<<4));
            }
            uint32_t b[NT][2];
            #pragma unroll
            for (int p=0;p<NT/2;p++){
                uint32_t r = wn*(BN/2) + p*16 + ((lane>>4)<<3) + (lane&7);
                uint32_t c = ks*2 + ((lane>>3)&1);
                uint32_t t[4];
                ldm4(t, ub + r*128 + ((c ^ (r&7))<<4));
                b[2*p][0]=t[0]; b[2*p][1]=t[1]; b[2*p+1][0]=t[2]; b[2*p+1][1]=t[3];
            }
            #pragma unroll
            for (int mt=0;mt<2;mt++)
                #pragma unroll
                for (int nt=0;nt<NT;nt++)
                    mma16816(acc[mt][nt], a[mt], b[nt]);
        }
    };

    const int nk = K >> 6;      // always >= 3
    load_stage(0,0); CP_COMMIT();
    load_stage(1,1); CP_COMMIT();
    for (int k0=0;k0<nk;k0++){
        CP_WAIT1();
        __syncthreads();
        if (k0+2 < nk) load_stage((k0+2)%3, k0+2);
        CP_COMMIT();
        compute_stage(k0%3);
    }

    #pragma unroll
    for (int mt=0;mt<2;mt++){
        #pragma unroll
        for (int nt=0;nt<NT;nt++){
            int m0 = wm*32 + mt*16 + (lane>>2);
            int n  = wn*(BN/2) + nt*8 + ((lane&3)<<1);
            #pragma unroll
            for (int h=0;h<2;h++){
                int m = m0 + h*8;
                float v0 = acc[mt][nt][2*h], v1 = acc[mt][nt][2*h+1];
                if (EPI==1){
                    *(float2*)((float*)Cv + (size_t)m*ldc + n) = make_float2(v0*scale, v1*scale);
                } else if (EPI==3){
                    float2 bb = *(const float2*)(bias + n);
                    float* p = (float*)Cv + (size_t)m*ldc + n;
                    float2 o = *(float2*)p;
                    *(float2*)p = make_float2(o.x+v0+bb.x, o.y+v1+bb.y);
                } else if (EPI==4){
                    float2 bb = *(const float2*)(bias + n);
                    float g0 = gelu_f(v0+bb.x), g1 = gelu_f(v1+bb.y);
                    bf16 h0,l0,h1,l1; split2(g0,h0,l0); split2(g1,h1,l1);
                    bf16* p = (bf16*)Cv + (size_t)m*ldc + n;
                    *(bf162*)p         = bf162(h0,h1);
                    *(bf162*)(p + seg) = bf162(l0,l1);
                } else if (EPI==5){
                    float2 bb = *(const float2*)(bias + n);
                    *(float2*)((float*)Cv + (size_t)m*ldc + n) = make_float2(v0+bb.x, v1+bb.y);
                } else if (EPI==6){
                    bf16 h0,l0,h1,l1; split2(v0,h0,l0); split2(v1,h1,l1);
                    bf16* p = (bf16*)Cv + (size_t)m*ldc + n;
                    *(bf162*)p         = bf162(h0,h1);
                    *(bf162*)(p + seg) = bf162(l0,l1);
                }
            }
        }
    }
}

// ---------------- GEMM wrappers ----------------
template<int EPI>
__global__ void __launch_bounds__(256,2) k_mma(
    const bf16* __restrict__ A, int lda,
    const bf16* __restrict__ Bt, int ldb,
    float* __restrict__ C, int ldc,
    const float* __restrict__ bias, int K, float scale, int ma, int mb)
{
    const int t=threadIdx.x, r=t>>3, co=(t&7)*8;
    const bf16* a[4]; const bf16* b[4];
    #pragma unroll
    for (int i=0;i<4;i++){
        a[i] = A  + (size_t)(blockIdx.y*128 + r + 32*i)*lda + co;
        b[i] = Bt + (size_t)(blockIdx.x*128 + r + 32*i)*ldb + co;
    }
    float* Ct = C + (size_t)blockIdx.y*128*ldc + blockIdx.x*128;
    const float* bi = bias ? bias + blockIdx.x*128 : (const float*)0;
    mma_core<128,EPI>(a[0],a[1],a[2],a[3],b[0],b[1],b[2],b[3],Ct,ldc,bi,K,scale,0,ma,mb);
}

__global__ void __launch_bounds__(256,2) k_scores_mma(){
    const int bh=blockIdx.z;
    const bf16* Q = g_qh + (size_t)bh*NSEQ*2*DH;
    const bf16* Kp= g_kh + (size_t)bh*NSEQ*2*DH;
    const int t=threadIdx.x, r=t>>3, co=(t&7)*8;
    const bf16* a[4]; const bf16* b[4];
    #pragma unroll
    for (int i=0;i<4;i++){
        a[i] = Q  + (size_t)(blockIdx.y*128 + r + 32*i)*(2*DH) + co;
        b[i] = Kp + (size_t)(blockIdx.x*128 + r + 32*i)*(2*DH) + co;
    }
    float* Ct = g_scores + (size_t)bh*NSEQ*NSEQ + (size_t)blockIdx.y*128*NSEQ + blockIdx.x*128;
    mma_core<128,1>(a[0],a[1],a[2],a[3],b[0],b[1],b[2],b[3],Ct,NSEQ,(const float*)0,3*DH,0.125f,0,1,1);
}

__global__ void __launch_bounds__(256,2) k_av_mma(){
    const int bh=blockIdx.z, b=bh>>3, h=bh&7;
    const bf16* A  = g_probsh + (size_t)bh*NSEQ*2*NSEQ;
    const bf16* Bt = g_vth + (size_t)bh*DH*2*NSEQ;
    const int t=threadIdx.x, r=t>>3, co=(t&7)*8;
    const bf16* a[4]; const bf16* bb[2];
    #pragma unroll
    for (int i=0;i<4;i++)
        a[i] = A + (size_t)(blockIdx.y*128 + r + 32*i)*(2*NSEQ) + co;
    #pragma unroll
    for (int i=0;i<2;i++)
        bb[i] = Bt + (size_t)(r + 32*i)*(2*NSEQ) + co;
    bf16* Ct = g_attnsp + (size_t)(b*NSEQ + blockIdx.y*128)*(2*DM) + h*DH;
    mma_core<64,6>(a[0],a[1],a[2],a[3],bb[0],bb[1],(const bf16*)0,(const bf16*)0,
                   Ct,2*DM,(const float*)0,3*NSEQ,1.f,DM,NSEQ/64,NSEQ/64);
}

template<int EPI, int GATHER>
__global__ void __launch_bounds__(256,2) k_moe_mma(
    const bf16* __restrict__ Abase, int lda,
    const bf16* __restrict__ BtAll, int ldb,
    void* __restrict__ Cbase, int ldc,
    const float* __restrict__ biasAll, int K, int N, int seg, int ma, int mb)
{
    const int e = g_map[blockIdx.y];
    if (e < 0) return;
    const bf16* Bt = BtAll + (size_t)e*N*(size_t)ldb;
    const float* bias = biasAll + (size_t)e*N + blockIdx.x*128;
    const int t=threadIdx.x, r=t>>3, co=(t&7)*8;
    const bf16* a[4]; const bf16* b[4];
    if (GATHER){
        const int lim = g_off[e] + g_cnt[e];
        #pragma unroll
        for (int i=0;i<4;i++){
            int s = blockIdx.y*128 + r + 32*i;
            int tok = (s < lim) ? g_tok[s] : 0;
            a[i] = Abase + (size_t)tok*lda + co;
        }
    } else {
        #pragma unroll
        for (int i=0;i<4;i++)
            a[i] = Abase + (size_t)(blockIdx.y*128 + r + 32*i)*lda + co;
    }
    #pragma unroll
    for (int i=0;i<4;i++)
        b[i] = Bt + (size_t)(blockIdx.x*128 + r + 32*i)*ldb + co;
    char* Ct;
    if (EPI==4) Ct = (char*)Cbase + ((size_t)blockIdx.y*128*ldc + blockIdx.x*128)*2;
    else        Ct = (char*)Cbase + ((size_t)blockIdx.y*128*ldc + blockIdx.x*128)*4;
    mma_core<128,EPI>(a[0],a[1],a[2],a[3],b[0],b[1],b[2],b[3],(void*)Ct,ldc,bias,K,1.f,seg,ma,mb);
}

// ---------------- conversions / transposes (2-wide splits) ----------------
// weight [R][C] fp32 -> [C][2R] bf16  (hi | lo)
__global__ void k_trw3(const float* __restrict__ in, bf16* __restrict__ out, int R, int C){
    __shared__ float tile[32][33];
    const float* I = in + (size_t)blockIdx.z*R*C;
    bf16* O = out + (size_t)blockIdx.z*R*C*2;
    int r0=blockIdx.y*32, c0=blockIdx.x*32;
    int x=threadIdx.x, y=threadIdx.y;
    #pragma unroll
    for (int i=0;i<4;i++) tile[y+8*i][x] = I[(size_t)(r0+y+8*i)*C + c0+x];
    __syncthreads();
    #pragma unroll
    for (int i=0;i<4;i++){
        float v = tile[x][y+8*i];
        bf16 hi, lo; split2(v, hi, lo);
        bf16* p = O + (size_t)(c0+y+8*i)*2*R + r0+x;
        p[0] = hi; p[R] = lo;
    }
}

// qkv fp32 -> 2-wide split Q and K, per head
__global__ void k_cvt_qk(){
    int gid = blockIdx.x*blockDim.x + threadIdx.x;   // TTOK*512
    int t = gid >> 9, c = gid & 511;
    int h = c >> 6, d = c & 63;
    int b = t >> 10, n = t & 1023;
    size_t base = ((size_t)(b*8+h)*NSEQ + n)*(2*DH);
    float qv = g_qkv[(size_t)t*QKVN + c];
    float kv = g_qkv[(size_t)t*QKVN + 512 + c];
    bf16 qh,ql,kh,kl; split2(qv,qh,ql); split2(kv,kh,kl);
    g_qh[base + d] = qh; g_qh[base + 64 + d] = ql;
    g_kh[base + d] = kh; g_kh[base + 64 + d] = kl;
}

// V slice of qkv fp32 -> transposed 2-wide split [bh][64][2*1024]
__global__ void k_trv3(){
    __shared__ float tile[32][33];
    int bh=blockIdx.z, b=bh>>3, h=bh&7;
    const float* I = g_qkv + (size_t)b*NSEQ*QKVN + 1024 + h*DH;
    bf16* O = g_vth + (size_t)bh*DH*2*NSEQ;
    int n0=blockIdx.y*32, d0=blockIdx.x*32;
    int x=threadIdx.x, y=threadIdx.y;
    #pragma unroll
    for (int i=0;i<4;i++) tile[y+8*i][x] = I[(size_t)(n0+y+8*i)*QKVN + d0+x];
    __syncthreads();
    #pragma unroll
    for (int i=0;i<4;i++){
        float v = tile[x][y+8*i];
        bf16 hi, lo; split2(v, hi, lo);
        bf16* p = O + (size_t)(d0+y+8*i)*2*NSEQ + n0+x;
        p[0] = hi; p[NSEQ] = lo;
    }
}

// ---------------- elementwise / routing ----------------
__global__ void k_copy4(const float4* __restrict__ in, float4* __restrict__ out, int n4){
    int i = blockIdx.x*blockDim.x + threadIdx.x;
    if (i < n4) out[i] = in[i];
}

template<int F32OUT>
__global__ void k_ln_h(const float* __restrict__ in, bf16* __restrict__ outh,
                       float* __restrict__ outf,
                       const float* __restrict__ w, const float* __restrict__ b){
    int t = blockIdx.x, i = threadIdx.x;
    float4 v = ((const float4*)(in + (size_t)t*DM))[i];
    float s  = v.x+v.y+v.z+v.w;
    float ss = v.x*v.x+v.y*v.y+v.z*v.z+v.w*v.w;
    #pragma unroll
    for (int o=16;o;o>>=1){ s += __shfl_xor_sync(0xffffffffu,s,o); ss += __shfl_xor_sync(0xffffffffu,ss,o); }
    __shared__ float sh_s[4], sh_q[4];
    int wid = i>>5, lane = i&31;
    if (lane==0){ sh_s[wid]=s; sh_q[wid]=ss; }
    __syncthreads();
    s  = sh_s[0]+sh_s[1]+sh_s[2]+sh_s[3];
    ss = sh_q[0]+sh_q[1]+sh_q[2]+sh_q[3];
    float mean = s * (1.0f/DM);
    float var  = ss * (1.0f/DM) - mean*mean;
    float inv  = rsqrtf(var + 1e-5f);
    float4 wv = ((const float4*)w)[i];
    float4 bv = ((const float4*)b)[i];
    float4 o;
    o.x=(v.x-mean)*inv*wv.x+bv.x; o.y=(v.y-mean)*inv*wv.y+bv.y;
    o.z=(v.z-mean)*inv*wv.z+bv.z; o.w=(v.w-mean)*inv*wv.w+bv.w;
    bf16* p = outh + (size_t)t*2*DM + 4*i;
    bf16 h0,l0,h1,l1,h2,l2,h3,l3;
    split2(o.x,h0,l0); split2(o.y,h1,l1); split2(o.z,h2,l2); split2(o.w,h3,l3);
    *(bf162*)(p)      = bf162(h0,h1); *(bf162*)(p+2)      = bf162(h2,h3);
    *(bf162*)(p+DM)   = bf162(l0,l1); *(bf162*)(p+DM+2)   = bf162(l2,l3);
    if (F32OUT) ((float4*)(outf + (size_t)t*DM))[i] = o;
}

__global__ void k_ln_f(const float* __restrict__ in, float* __restrict__ out,
                       const float* __restrict__ w, const float* __restrict__ b){
    int t = blockIdx.x, i = threadIdx.x;
    float4 v = ((const float4*)(in + (size_t)t*DM))[i];
    float s  = v.x+v.y+v.z+v.w;
    float ss = v.x*v.x+v.y*v.y+v.z*v.z+v.w*v.w;
    #pragma unroll
    for (int o=16;o;o>>=1){ s += __shfl_xor_sync(0xffffffffu,s,o); ss += __shfl_xor_sync(0xffffffffu,ss,o); }
    __shared__ float sh_s[4], sh_q[4];
    int wid = i>>5, lane = i&31;
    if (lane==0){ sh_s[wid]=s; sh_q[wid]=ss; }
    __syncthreads();
    s  = sh_s[0]+sh_s[1]+sh_s[2]+sh_s[3];
    ss = sh_q[0]+sh_q[1]+sh_q[2]+sh_q[3];
    float mean = s * (1.0f/DM);
    float var  = ss * (1.0f/DM) - mean*mean;
    float inv  = rsqrtf(var + 1e-5f);
    float4 wv = ((const float4*)w)[i];
    float4 bv = ((const float4*)b)[i];
    float4 o;
    o.x=(v.x-mean)*inv*wv.x+bv.x; o.y=(v.y-mean)*inv*wv.y+bv.y;
    o.z=(v.z-mean)*inv*wv.z+bv.z; o.w=(v.w-mean)*inv*wv.w+bv.w;
    ((float4*)(out + (size_t)t*DM))[i] = o;
}

__global__ void k_softmax(){
    const float* row = g_scores + (size_t)blockIdx.x*NSEQ;
    bf16* orow = g_probsh + (size_t)blockIdx.x*2*NSEQ;
    int i = threadIdx.x;
    float4 v = ((const float4*)row)[i];
    float m = fmaxf(fmaxf(v.x,v.y), fmaxf(v.z,v.w));
    #pragma unroll
    for (int o=16;o;o>>=1) m = fmaxf(m, __shfl_xor_sync(0xffffffffu,m,o));
    __shared__ float sh[8];
    int wid = i>>5, lane = i&31;
    if (lane==0) sh[wid]=m;
    __syncthreads();
    float bm = sh[0];
    #pragma unroll
    for (int w=1;w<8;w++) bm = fmaxf(bm, sh[w]);
    v.x = __expf(v.x-bm); v.y = __expf(v.y-bm); v.z = __expf(v.z-bm); v.w = __expf(v.w-bm);
    float s = v.x+v.y+v.z+v.w;
    #pragma unroll
    for (int o=16;o;o>>=1) s += __shfl_xor_sync(0xffffffffu,s,o);
    __syncthreads();
    if (lane==0) sh[wid]=s;
    __syncthreads();
    float bs = sh[0]+sh[1]+sh[2]+sh[3]+sh[4]+sh[5]+sh[6]+sh[7];
    float inv = 1.0f/bs;
    v.x*=inv; v.y*=inv; v.z*=inv; v.w*=inv;
    bf16 h0,l0,h1,l1,h2,l2,h3,l3;
    split2(v.x,h0,l0); split2(v.y,h1,l1); split2(v.z,h2,l2); split2(v.w,h3,l3);
    bf16* p = orow + 4*i;
    *(bf162*)(p)      = bf162(h0,h1); *(bf162*)(p+2)      = bf162(h2,h3);
    *(bf162*)(p+NSEQ) = bf162(l0,l1); *(bf162*)(p+NSEQ+2) = bf162(l2,l3);
}

__global__ void k_gate(const float* __restrict__ wg){
    int gid = blockIdx.x*blockDim.x + threadIdx.x;
    if (gid >= TTOK*NE) return;
    int t = gid>>3, e = gid&7;
    const float* xr = g_y + (size_t)t*DM;
    float s = 0.f;
    #pragma unroll 8
    for (int k=0;k<DM;k++) s = fmaf(xr[k], wg[k*NE+e], s);
    g_logits[t*NE+e] = s;
}

__global__ void k_zero_cnt(){ if (threadIdx.x < NE) g_cnt[threadIdx.x] = 0; }

__global__ void k_top2(){
    int t = blockIdx.x*blockDim.x + threadIdx.x;
    if (t >= TTOK) return;
    const float* lr = g_logits + t*NE;
    int i0 = 0; float v0 = lr[0];
    #pragma unroll
    for (int e=1;e<NE;e++){ float v = lr[e]; if (v > v0){ v0=v; i0=e; } }
    int i1 = -1; float v1 = -3.4e38f;
    #pragma unroll
    for (int e=0;e<NE;e++){ if (e==i0) continue; float v = lr[e]; if (v > v1){ v1=v; i1=e; } }
    float e1v = expf(v1 - v0);
    float inv = 1.0f/(1.0f + e1v);
    g_e0[t]=i0; g_e1i[t]=i1;
    g_g0[t]=inv; g_g1[t]=e1v*inv;
    atomicAdd(&g_cnt[i0],1);
    atomicAdd(&g_cnt[i1],1);
}

__global__ void k_scan(){
    int off = 0, rb = 0;
    for (int e=0;e<NE;e++){
        g_off[e] = off; g_cur[e] = off;
        int nb = (g_cnt[e] + 127) >> 7;
        for (int i=0;i<nb;i++) g_map[rb++] = e;
        off += nb*128;
    }
    for (; rb<MAXRB; rb++) g_map[rb] = -1;
}

__global__ void k_scatter(){
    int t = blockIdx.x*blockDim.x + threadIdx.x;
    if (t >= TTOK) return;
    int p0 = atomicAdd(&g_cur[g_e0[t]], 1);  g_tok[p0]=t; g_slotA[t]=p0;
    int p1 = atomicAdd(&g_cur[g_e1i[t]], 1); g_tok[p1]=t; g_slotB[t]=p1;
}

__global__ void k_combine(){
    int t = blockIdx.x, i = threadIdx.x;
    float gg0 = g_g0[t], gg1 = g_g1[t];
    float4 a = ((const float4*)(g_y2 + (size_t)g_slotA[t]*DM))[i];
    float4 b = ((const float4*)(g_y2 + (size_t)g_slotB[t]*DM))[i];
    float4* xr = (float4*)(g_x + (size_t)t*DM);
    float4 xv = xr[i];
    xv.x += gg0*a.x + gg1*b.x;
    xv.y += gg0*a.y + gg1*b.y;
    xv.z += gg0*a.z + gg1*b.z;
    xv.w += gg0*a.w + gg1*b.w;
    xr[i] = xv;
}

// ---------------- host orchestration ----------------
#define SMEM128 (3*(16384 + 128*128))   /* 98304 */
#define SMEM64  (3*(16384 +  64*128))   /* 73728 */

extern "C" void kernel_launch(void* const* d_in, const int* in_sizes, int n_in,
                              void* d_out, int out_size){
    (void)in_sizes; (void)n_in; (void)out_size;
    const float* x    = (const float*)d_in[0];
    const float* ln1w = (const float*)d_in[1];
    const float* ln1b = (const float*)d_in[2];
    const float* qkvw = (const float*)d_in[3];
    const float* outw = (const float*)d_in[4];
    const float* outb = (const float*)d_in[5];
    const float* ln2w = (const float*)d_in[6];
    const float* ln2b = (const float*)d_in[7];
    const float* wg   = (const float*)d_in[8];
    const float* ew1  = (const float*)d_in[9];
    const float* eb1  = (const float*)d_in[10];
    const float* ew2  = (const float*)d_in[11];
    const float* eb2  = (const float*)d_in[12];
    const float* flnw = (const float*)d_in[13];
    const float* flnb = (const float*)d_in[14];
    float* out = (float*)d_out;

    float *px, *py, *pq, *py2;
    bf16 *pyh, *phh, *pattnsp, *pqkvT, *poutT, *pe1T, *pe2T;
    cudaGetSymbolAddress((void**)&px,   g_x);
    cudaGetSymbolAddress((void**)&py,   g_y);
    cudaGetSymbolAddress((void**)&pq,   g_qkv);
    cudaGetSymbolAddress((void**)&py2,  g_y2);
    cudaGetSymbolAddress((void**)&pyh,  g_yh);
    cudaGetSymbolAddress((void**)&phh,  g_hh);
    cudaGetSymbolAddress((void**)&pattnsp, g_attnsp);
    cudaGetSymbolAddress((void**)&pqkvT,g_qkvwT);
    cudaGetSymbolAddress((void**)&poutT,g_outwT);
    cudaGetSymbolAddress((void**)&pe1T, g_e1T);
    cudaGetSymbolAddress((void**)&pe2T, g_e2T);

    cudaFuncSetAttribute(k_mma<1>, cudaFuncAttributeMaxDynamicSharedMemorySize, SMEM128);
    cudaFuncSetAttribute(k_mma<3>, cudaFuncAttributeMaxDynamicSharedMemorySize, SMEM128);
    cudaFuncSetAttribute(k_scores_mma, cudaFuncAttributeMaxDynamicSharedMemorySize, SMEM128);
    cudaFuncSetAttribute(k_av_mma, cudaFuncAttributeMaxDynamicSharedMemorySize, SMEM64);
    cudaFuncSetAttribute(k_moe_mma<4,1>, cudaFuncAttributeMaxDynamicSharedMemorySize, SMEM128);
    cudaFuncSetAttribute(k_moe_mma<5,0>, cudaFuncAttributeMaxDynamicSharedMemorySize, SMEM128);

    {   int n4 = TTOK*DM/4;
        k_copy4<<<(n4+255)/256, 256>>>((const float4*)x, (float4*)px, n4); }

    // weight transpose + 2-wide bf16 split
    k_trw3<<<dim3(QKVN/32, DM/32, NL), dim3(32,8)>>>(qkvw, pqkvT, DM, QKVN);
    k_trw3<<<dim3(DM/32,   DM/32, NL), dim3(32,8)>>>(outw, poutT, DM, DM);
    k_trw3<<<dim3(HFF/32,  DM/32, NL*NE), dim3(32,8)>>>(ew1, pe1T, DM, HFF);
    k_trw3<<<dim3(DM/32,  HFF/32, NL*NE), dim3(32,8)>>>(ew2, pe2T, HFF, DM);

    for (int l=0;l<NL;l++){
        // ---- attention ----
        k_ln_h<0><<<TTOK,128>>>(px, pyh, (float*)0, ln1w + l*DM, ln1b + l*DM);
        k_mma<1><<<dim3(QKVN/128, TTOK/128), 256, SMEM128>>>(
            pyh, 2*DM, pqkvT + (size_t)l*QKVN*2*DM, 2*DM, pq, QKVN,
            (const float*)0, 3*DM, 1.f, DM/64, DM/64);
        k_cvt_qk<<<(TTOK*512)/256, 256>>>();
        k_trv3<<<dim3(2, NSEQ/32, 64), dim3(32,8)>>>();
        k_scores_mma<<<dim3(NSEQ/128, NSEQ/128, 64), 256, SMEM128>>>();
        k_softmax<<<64*NSEQ, 256>>>();
        k_av_mma<<<dim3(1, NSEQ/128, 64), 256, SMEM64>>>();
        k_mma<3><<<dim3(DM/128, TTOK/128), 256, SMEM128>>>(
            pattnsp, 2*DM, poutT + (size_t)l*DM*2*DM, 2*DM, px, DM,
            outb + l*DM, 3*DM, 1.f, DM/64, DM/64);
        // ---- MoE ----
        k_ln_h<1><<<TTOK,128>>>(px, pyh, py, ln2w + l*DM, ln2b + l*DM);
        k_zero_cnt<<<1,32>>>();
        k_gate<<<(TTOK*NE)/256, 256>>>(wg + (size_t)l*DM*NE);
        k_top2<<<TTOK/256, 256>>>();
        k_scan<<<1,1>>>();
        k_scatter<<<TTOK/256, 256>>>();
        k_moe_mma<4,1><<<dim3(HFF/128, MAXRB), 256, SMEM128>>>(
            pyh, 2*DM, pe1T + (size_t)l*NE*HFF*2*DM, 2*DM, phh, 2*HFF,
            eb1 + (size_t)l*NE*HFF, 3*DM, HFF, HFF, DM/64, DM/64);
        k_moe_mma<5,0><<<dim3(DM/128, MAXRB), 256, SMEM128>>>(
            phh, 2*HFF, pe2T + (size_t)l*NE*DM*2*HFF, 2*HFF, py2, DM,
            eb2 + (size_t)l*NE*DM, 3*HFF, DM, 0, HFF/64, HFF/64);
        k_combine<<<TTOK,128>>>();
    }

    k_ln_f<<<TTOK,128>>>(px, out, flnw, flnb);
}

// round 7
// speedup vs baseline: 2.7454x; 1.0716x over previous
#include <cuda_runtime.h>
#include <cuda_bf16.h>
#include <math.h>
#include <stdint.h>

#define TTOK 8192
#define DM   512
#define QKVN 1536
#define HFF  2048
#define NE   8
#define NSEQ 1024
#define DH   64
#define NL   4
#define SLOTMAX (2*TTOK + NE*128)   /* 17408 */
#define MAXRB   (SLOTMAX/128)       /* 136   */

typedef __nv_bfloat16  bf16;
typedef __nv_bfloat162 bf162;

// ---------------- static device scratch (splits stored 2-wide: [hi|lo]) ----------------
__device__ __align__(128) float g_x[TTOK*DM];
__device__ __align__(128) float g_y[TTOK*DM];
__device__ __align__(128) float g_qkv[(size_t)TTOK*QKVN];
__device__ __align__(128) float g_y2[(size_t)SLOTMAX*DM];
__device__ __align__(128) float g_logits[TTOK*NE];
__device__ __align__(128) bf16  g_yh[(size_t)TTOK*2*DM];
__device__ __align__(128) bf16  g_qh[(size_t)64*NSEQ*2*DH];
__device__ __align__(128) bf16  g_kh[(size_t)64*NSEQ*2*DH];
__device__ __align__(128) bf16  g_vth[(size_t)64*DH*2*NSEQ];
__device__ __align__(128) bf16  g_attnsp[(size_t)TTOK*2*DM];
__device__ __align__(128) bf16  g_hh[(size_t)SLOTMAX*2*HFF];
__device__ __align__(128) bf16  g_qkvwT[(size_t)NL*QKVN*2*DM];
__device__ __align__(128) bf16  g_outwT[(size_t)NL*DM*2*DM];
__device__ __align__(128) bf16  g_e1T[(size_t)NL*NE*HFF*2*DM];
__device__ __align__(128) bf16  g_e2T[(size_t)NL*NE*DM*2*HFF];
__device__ int   g_e0[TTOK], g_e1i[TTOK];
__device__ float g_g0[TTOK], g_g1[TTOK];
__device__ int   g_cnt[NE], g_off[NE], g_cur[NE];
__device__ int   g_map[MAXRB];
__device__ int   g_tok[SLOTMAX];
__device__ int   g_slotA[TTOK], g_slotB[TTOK];

// ---------------- low-level helpers ----------------
__device__ __forceinline__ uint32_t smem_u32(const void* p){
    uint32_t a; asm("{ .reg .u64 t; cvta.to.shared.u64 t, %1; cvt.u32.u64 %0, t; }":"=r"(a):"l"(p)); return a;
}
__device__ __forceinline__ void cpasync16(uint32_t dst, const void* src){
    asm volatile("cp.async.cg.shared.global [%0], [%1], 16;" :: "r"(dst), "l"(src));
}
#define CP_COMMIT() asm volatile("cp.async.commit_group;" ::: "memory")
#define CP_WAIT1()  asm volatile("cp.async.wait_group 1;" ::: "memory")
#define CP_WAIT0()  asm volatile("cp.async.wait_group 0;" ::: "memory")
__device__ __forceinline__ void ldm4(uint32_t* r, uint32_t a){
    asm volatile("ldmatrix.sync.aligned.m8n8.x4.shared.b16 {%0,%1,%2,%3}, [%4];"
        : "=r"(r[0]),"=r"(r[1]),"=r"(r[2]),"=r"(r[3]) : "r"(a));
}
__device__ __forceinline__ void mma16816(float* c, const uint32_t* a, const uint32_t* b){
    asm volatile("mma.sync.aligned.m16n8k16.row.col.f32.bf16.bf16.f32 "
        "{%0,%1,%2,%3}, {%4,%5,%6,%7}, {%8,%9}, {%0,%1,%2,%3};"
        : "+f"(c[0]),"+f"(c[1]),"+f"(c[2]),"+f"(c[3])
        : "r"(a[0]),"r"(a[1]),"r"(a[2]),"r"(a[3]), "r"(b[0]),"r"(b[1]));
}
__device__ __forceinline__ float gelu_f(float x){ return 0.5f*x*(1.f+erff(x*0.70710678118654752f)); }
__device__ __forceinline__ void split2(float v, bf16& hi, bf16& lo){
    hi = __float2bfloat16_rn(v);
    lo = __float2bfloat16_rn(v - __bfloat162float(hi));
}

// ---------------- bf16 mma GEMM core (3-stage cp.async, occ 2) ----------------
// Logical C[128,BN] = A[128, 3*Ko] x Bt[BN, 3*Ko]^T with A segs [hi,lo,hi], B segs [hi,hi,lo],
// storage 2-wide [hi|lo]; chunk remap: ca = c<2ma? c : c-2ma ; cb = c<mb? c : c-mb.
// EPI: 1 fp32 out *scale; 3 fp32 RMW +bias (residual); 4 gelu(+bias)->2-seg bf16 (seg); 5 fp32 out +bias
template<int BN, int EPI>
__device__ __forceinline__ void mma_core(
    const bf16* a0,const bf16* a1,const bf16* a2,const bf16* a3,
    const bf16* b0,const bf16* b1,const bf16* b2,const bf16* b3,
    void* Cv, int ldc, const float* bias, int K, float scale, int seg, int ma, int mb)
{
    extern __shared__ __align__(128) char dsm[];
    constexpr int STAGE = 16384 + BN*128;
    const uint32_t sb = smem_u32(dsm);
    const int tid = threadIdx.x;
    const int lane = tid & 31, wid = tid >> 5;
    const int wm = wid & 3, wn = wid >> 2;
    const bf16* Ar[4] = {a0,a1,a2,a3};
    const bf16* Br[4] = {b0,b1,b2,b3};
    constexpr int NBR = BN/32;
    constexpr int NT  = BN/16;

    float acc[2][NT][4];
    #pragma unroll
    for (int mt=0;mt<2;mt++)
        #pragma unroll
        for (int nt=0;nt<NT;nt++)
            #pragma unroll
            for (int q=0;q<4;q++) acc[mt][nt][q]=0.f;

    const int r8 = tid>>3, cu = tid&7;
    auto load_stage = [&](int st, int kc){
        const int ca = (kc < 2*ma) ? kc : kc - 2*ma;
        const int cb = (kc < mb)   ? kc : kc - mb;
        uint32_t ua = sb + st*STAGE;
        uint32_t ub = ua + 16384;
        #pragma unroll
        for (int i=0;i<4;i++){
            uint32_t ro = r8 + 32*i;
            cpasync16(ua + ro*128 + ((cu ^ (ro&7))<<4), Ar[i] + ca*64);
        }
        #pragma unroll
        for (int i=0;i<NBR;i++){
            uint32_t ro = r8 + 32*i;
            cpasync16(ub + ro*128 + ((cu ^ (ro&7))<<4), Br[i] + cb*64);
        }
    };
    auto compute_stage = [&](int st){
        uint32_t ua = sb + st*STAGE;
        uint32_t ub = ua + 16384;
        #pragma unroll
        for (int ks=0;ks<4;ks++){
            uint32_t a[2][4];
            #pragma unroll
            for (int mt=0;mt<2;mt++){
                uint32_t r = wm*32 + mt*16 + (lane&15);
                uint32_t c = ks*2 + (lane>>4);
                ldm4(a[mt], ua + r*128 + ((c ^ (r&7))<<4));
            }
            uint32_t b[NT][2];
            #pragma unroll
            for (int p=0;p<NT/2;p++){
                uint32_t r = wn*(BN/2) + p*16 + ((lane>>4)<<3) + (lane&7);
                uint32_t c = ks*2 + ((lane>>3)&1);
                uint32_t t[4];
                ldm4(t, ub + r*128 + ((c ^ (r&7))<<4));
                b[2*p][0]=t[0]; b[2*p][1]=t[1]; b[2*p+1][0]=t[2]; b[2*p+1][1]=t[3];
            }
            #pragma unroll
            for (int mt=0;mt<2;mt++)
                #pragma unroll
                for (int nt=0;nt<NT;nt++)
                    mma16816(acc[mt][nt], a[mt], b[nt]);
        }
    };

    const int nk = K >> 6;
    load_stage(0,0); CP_COMMIT();
    load_stage(1,1); CP_COMMIT();
    for (int k0=0;k0<nk;k0++){
        CP_WAIT1();
        __syncthreads();
        if (k0+2 < nk) load_stage((k0+2)%3, k0+2);
        CP_COMMIT();
        compute_stage(k0%3);
    }

    #pragma unroll
    for (int mt=0;mt<2;mt++){
        #pragma unroll
        for (int nt=0;nt<NT;nt++){
            int m0 = wm*32 + mt*16 + (lane>>2);
            int n  = wn*(BN/2) + nt*8 + ((lane&3)<<1);
            #pragma unroll
            for (int h=0;h<2;h++){
                int m = m0 + h*8;
                float v0 = acc[mt][nt][2*h], v1 = acc[mt][nt][2*h+1];
                if (EPI==1){
                    *(float2*)((float*)Cv + (size_t)m*ldc + n) = make_float2(v0*scale, v1*scale);
                } else if (EPI==3){
                    float2 bb = *(const float2*)(bias + n);
                    float* p = (float*)Cv + (size_t)m*ldc + n;
                    float2 o = *(float2*)p;
                    *(float2*)p = make_float2(o.x+v0+bb.x, o.y+v1+bb.y);
                } else if (EPI==4){
                    float2 bb = *(const float2*)(bias + n);
                    float g0 = gelu_f(v0+bb.x), g1 = gelu_f(v1+bb.y);
                    bf16 h0,l0,h1,l1; split2(g0,h0,l0); split2(g1,h1,l1);
                    bf16* p = (bf16*)Cv + (size_t)m*ldc + n;
                    *(bf162*)p         = bf162(h0,h1);
                    *(bf162*)(p + seg) = bf162(l0,l1);
                } else if (EPI==5){
                    float2 bb = *(const float2*)(bias + n);
                    *(float2*)((float*)Cv + (size_t)m*ldc + n) = make_float2(v0+bb.x, v1+bb.y);
                }
            }
        }
    }
}

// ---------------- GEMM wrappers ----------------
template<int EPI>
__global__ void __launch_bounds__(256,2) k_mma(
    const bf16* __restrict__ A, int lda,
    const bf16* __restrict__ Bt, int ldb,
    float* __restrict__ C, int ldc,
    const float* __restrict__ bias, int K, float scale, int ma, int mb)
{
    const int t=threadIdx.x, r=t>>3, co=(t&7)*8;
    const bf16* a[4]; const bf16* b[4];
    #pragma unroll
    for (int i=0;i<4;i++){
        a[i] = A  + (size_t)(blockIdx.y*128 + r + 32*i)*lda + co;
        b[i] = Bt + (size_t)(blockIdx.x*128 + r + 32*i)*ldb + co;
    }
    float* Ct = C + (size_t)blockIdx.y*128*ldc + blockIdx.x*128;
    const float* bi = bias ? bias + blockIdx.x*128 : (const float*)0;
    mma_core<128,EPI>(a[0],a[1],a[2],a[3],b[0],b[1],b[2],b[3],Ct,ldc,bi,K,scale,0,ma,mb);
}

template<int EPI, int GATHER>
__global__ void __launch_bounds__(256,2) k_moe_mma(
    const bf16* __restrict__ Abase, int lda,
    const bf16* __restrict__ BtAll, int ldb,
    void* __restrict__ Cbase, int ldc,
    const float* __restrict__ biasAll, int K, int N, int seg, int ma, int mb)
{
    const int e = g_map[blockIdx.y];
    if (e < 0) return;
    const bf16* Bt = BtAll + (size_t)e*N*(size_t)ldb;
    const float* bias = biasAll + (size_t)e*N + blockIdx.x*128;
    const int t=threadIdx.x, r=t>>3, co=(t&7)*8;
    const bf16* a[4]; const bf16* b[4];
    if (GATHER){
        const int lim = g_off[e] + g_cnt[e];
        #pragma unroll
        for (int i=0;i<4;i++){
            int s = blockIdx.y*128 + r + 32*i;
            int tok = (s < lim) ? g_tok[s] : 0;
            a[i] = Abase + (size_t)tok*lda + co;
        }
    } else {
        #pragma unroll
        for (int i=0;i<4;i++)
            a[i] = Abase + (size_t)(blockIdx.y*128 + r + 32*i)*lda + co;
    }
    #pragma unroll
    for (int i=0;i<4;i++)
        b[i] = Bt + (size_t)(blockIdx.x*128 + r + 32*i)*ldb + co;
    char* Ct;
    if (EPI==4) Ct = (char*)Cbase + ((size_t)blockIdx.y*128*ldc + blockIdx.x*128)*2;
    else        Ct = (char*)Cbase + ((size_t)blockIdx.y*128*ldc + blockIdx.x*128)*4;
    mma_core<128,EPI>(a[0],a[1],a[2],a[3],b[0],b[1],b[2],b[3],(void*)Ct,ldc,bias,K,1.f,seg,ma,mb);
}

// ---------------- fused flash attention ----------------
// grid (NSEQ/128, 64 bh), 256 thr, occ 2.
// smem: Q 2ch x128x128B @0 (32K); K 2ch x64x128B @32768 (16K); V 2ch x64x128B @49152 (16K);
//       P 2ch x128x128B @65536 (32K); Rm @98304 (1K); Rs @99328 (1K). total 100352.
#define FSMEM 100352
__global__ void __launch_bounds__(256,2) k_flash(){
    extern __shared__ __align__(128) char dsm[];
    const uint32_t sb = smem_u32(dsm);
    const uint32_t uQ = sb, uK = sb+32768, uV = sb+49152, uP = sb+65536;
    float* Rm = (float*)(dsm + 98304);
    float* Rs = (float*)(dsm + 99328);
    const int bh = blockIdx.y, q0 = blockIdx.x*128;
    const int bb_ = bh>>3, head = bh&7;
    const int tid = threadIdx.x, lane = tid&31, wid = tid>>5;
    const int wm = wid&3, wn = wid>>2;

    const bf16* Qg = g_qh + ((size_t)bh*NSEQ + q0)*(2*DH);
    const bf16* Kg0 = g_kh + (size_t)bh*NSEQ*(2*DH);
    const bf16* Vg0 = g_vth + (size_t)bh*DH*2*NSEQ;

    auto loadK = [&](int j){
        const bf16* Kg = Kg0 + (size_t)(j*64)*(2*DH);
        #pragma unroll
        for (int i=0;i<2;i++){
            int idx = tid + i*256;
            int row = idx>>3, cu = idx&7;
            uint32_t sw = (uint32_t)((cu ^ (row&7))<<4);
            cpasync16(uK + row*128 + sw, Kg + (size_t)row*(2*DH) + cu*8);
            cpasync16(uK + 8192 + row*128 + sw, Kg + (size_t)row*(2*DH) + 64 + cu*8);
        }
    };
    auto loadV = [&](int j){
        const bf16* Vg = Vg0 + j*64;
        #pragma unroll
        for (int i=0;i<2;i++){
            int idx = tid + i*256;
            int row = idx>>3, cu = idx&7;
            uint32_t sw = (uint32_t)((cu ^ (row&7))<<4);
            cpasync16(uV + row*128 + sw, Vg + (size_t)row*2*NSEQ + cu*8);
            cpasync16(uV + 8192 + row*128 + sw, Vg + (size_t)row*2*NSEQ + NSEQ + cu*8);
        }
    };

    // prologue: Q + K(0) + V(0)
    #pragma unroll
    for (int i=0;i<4;i++){
        int idx = tid + i*256;
        int row = idx>>3, cu = idx&7;
        uint32_t sw = (uint32_t)((cu ^ (row&7))<<4);
        cpasync16(uQ + row*128 + sw, Qg + (size_t)row*(2*DH) + cu*8);
        cpasync16(uQ + 16384 + row*128 + sw, Qg + (size_t)row*(2*DH) + 64 + cu*8);
    }
    loadK(0); loadV(0); CP_COMMIT();

    float Oacc[2][4][4];
    #pragma unroll
    for (int mt=0;mt<2;mt++)
        #pragma unroll
        for (int nt=0;nt<4;nt++)
            #pragma unroll
            for (int q=0;q<4;q++) Oacc[mt][nt][q]=0.f;
    float mrow[2][2], lrow[2][2];
    #pragma unroll
    for (int mt=0;mt<2;mt++){ mrow[mt][0]=-1e30f; mrow[mt][1]=-1e30f; lrow[mt][0]=0.f; lrow[mt][1]=0.f; }

    const int qcs[3]={0,1,0}, kcs[3]={0,0,1};

    for (int j=0;j<16;j++){
        CP_WAIT0();
        __syncthreads();

        // ---- S = Q K^T (3-term) ----
        float S[2][4][4];
        #pragma unroll
        for (int mt=0;mt<2;mt++)
            #pragma unroll
            for (int nt=0;nt<4;nt++)
                #pragma unroll
                for (int q=0;q<4;q++) S[mt][nt][q]=0.f;
        #pragma unroll
        for (int r3=0;r3<3;r3++){
            uint32_t qb = uQ + qcs[r3]*16384;
            uint32_t kb = uK + kcs[r3]*8192;
            #pragma unroll
            for (int ks=0;ks<4;ks++){
                uint32_t a[2][4];
                #pragma unroll
                for (int mt=0;mt<2;mt++){
                    uint32_t r = wm*32 + mt*16 + (lane&15);
                    uint32_t c = ks*2 + (lane>>4);
                    ldm4(a[mt], qb + r*128 + ((c ^ (r&7))<<4));
                }
                uint32_t b[4][2];
                #pragma unroll
                for (int p=0;p<2;p++){
                    uint32_t r = wn*32 + p*16 + ((lane>>4)<<3) + (lane&7);
                    uint32_t c = ks*2 + ((lane>>3)&1);
                    uint32_t t4[4];
                    ldm4(t4, kb + r*128 + ((c ^ (r&7))<<4));
                    b[2*p][0]=t4[0]; b[2*p][1]=t4[1]; b[2*p+1][0]=t4[2]; b[2*p+1][1]=t4[3];
                }
                #pragma unroll
                for (int mt=0;mt<2;mt++)
                    #pragma unroll
                    for (int nt=0;nt<4;nt++)
                        mma16816(S[mt][nt], a[mt], b[nt]);
            }
        }
        #pragma unroll
        for (int mt=0;mt<2;mt++)
            #pragma unroll
            for (int nt=0;nt<4;nt++)
                #pragma unroll
                for (int q=0;q<4;q++) S[mt][nt][q] *= 0.125f;

        // ---- row max ----
        #pragma unroll
        for (int mt=0;mt<2;mt++)
            #pragma unroll
            for (int hh=0;hh<2;hh++){
                float pm = -1e30f;
                #pragma unroll
                for (int nt=0;nt<4;nt++){
                    pm = fmaxf(pm, S[mt][nt][2*hh]);
                    pm = fmaxf(pm, S[mt][nt][2*hh+1]);
                }
                pm = fmaxf(pm, __shfl_xor_sync(0xffffffffu, pm, 1));
                pm = fmaxf(pm, __shfl_xor_sync(0xffffffffu, pm, 2));
                int rloc = wm*32 + mt*16 + (lane>>2) + 8*hh;
                if ((lane&3)==0) Rm[rloc*2 + wn] = pm;
            }
        __syncthreads();

        float mnewA[2][2], sfA[2][2];
        #pragma unroll
        for (int mt=0;mt<2;mt++)
            #pragma unroll
            for (int hh=0;hh<2;hh++){
                int rloc = wm*32 + mt*16 + (lane>>2) + 8*hh;
                float mj = fmaxf(Rm[rloc*2], Rm[rloc*2+1]);
                float mn = fmaxf(mrow[mt][hh], mj);
                float sf = __expf(mrow[mt][hh] - mn);
                mrow[mt][hh] = mn; mnewA[mt][hh] = mn; sfA[mt][hh] = sf;
                lrow[mt][hh] *= sf;
                #pragma unroll
                for (int nt=0;nt<4;nt++){
                    Oacc[mt][nt][2*hh]   *= sf;
                    Oacc[mt][nt][2*hh+1] *= sf;
                }
            }
        // prefetch K(j+1) — all warps past QK ldmatrix (barrier above)
        if (j+1<16){ loadK(j+1); CP_COMMIT(); }

        // ---- exp, split->P smem, partial sums ----
        float ps[2][2]; ps[0][0]=0.f; ps[0][1]=0.f; ps[1][0]=0.f; ps[1][1]=0.f;
        #pragma unroll
        for (int mt=0;mt<2;mt++)
            #pragma unroll
            for (int nt=0;nt<4;nt++)
                #pragma unroll
                for (int hh=0;hh<2;hh++){
                    float p0 = __expf(S[mt][nt][2*hh]   - mnewA[mt][hh]);
                    float p1 = __expf(S[mt][nt][2*hh+1] - mnewA[mt][hh]);
                    ps[mt][hh] += p0 + p1;
                    bf16 h0,l0,h1,l1; split2(p0,h0,l0); split2(p1,h1,l1);
                    int rloc = wm*32 + mt*16 + (lane>>2) + 8*hh;
                    int c = wn*32 + nt*8 + (lane&3)*2;
                    uint32_t off = (uint32_t)rloc*128 + (uint32_t)((((c>>3) ^ (rloc&7))<<4) + (c&7)*2);
                    *(bf162*)(dsm + 65536 + off)         = bf162(h0,h1);
                    *(bf162*)(dsm + 65536 + 16384 + off) = bf162(l0,l1);
                }
        #pragma unroll
        for (int mt=0;mt<2;mt++)
            #pragma unroll
            for (int hh=0;hh<2;hh++){
                float s = ps[mt][hh];
                s += __shfl_xor_sync(0xffffffffu, s, 1);
                s += __shfl_xor_sync(0xffffffffu, s, 2);
                int rloc = wm*32 + mt*16 + (lane>>2) + 8*hh;
                if ((lane&3)==0) Rs[rloc*2 + wn] = s;
            }
        __syncthreads();
        #pragma unroll
        for (int mt=0;mt<2;mt++)
            #pragma unroll
            for (int hh=0;hh<2;hh++){
                int rloc = wm*32 + mt*16 + (lane>>2) + 8*hh;
                lrow[mt][hh] += Rs[rloc*2] + Rs[rloc*2+1];
            }

        // ---- O += P V^T (3-term) ----
        const int pcs[3]={0,1,0}, vcs[3]={0,0,1};
        #pragma unroll
        for (int r3=0;r3<3;r3++){
            uint32_t pb = uP + pcs[r3]*16384;
            uint32_t vb = uV + vcs[r3]*8192;
            #pragma unroll
            for (int ks=0;ks<4;ks++){
                uint32_t a[2][4];
                #pragma unroll
                for (int mt=0;mt<2;mt++){
                    uint32_t r = wm*32 + mt*16 + (lane&15);
                    uint32_t c = ks*2 + (lane>>4);
                    ldm4(a[mt], pb + r*128 + ((c ^ (r&7))<<4));
                }
                uint32_t b[4][2];
                #pragma unroll
                for (int p=0;p<2;p++){
                    uint32_t r = wn*32 + p*16 + ((lane>>4)<<3) + (lane&7);
                    uint32_t c = ks*2 + ((lane>>3)&1);
                    uint32_t t4[4];
                    ldm4(t4, vb + r*128 + ((c ^ (r&7))<<4));
                    b[2*p][0]=t4[0]; b[2*p][1]=t4[1]; b[2*p+1][0]=t4[2]; b[2*p+1][1]=t4[3];
                }
                #pragma unroll
                for (int mt=0;mt<2;mt++)
                    #pragma unroll
                    for (int nt=0;nt<4;nt++)
                        mma16816(Oacc[mt][nt], a[mt], b[nt]);
            }
        }
        __syncthreads();       // V/P ldmatrix complete before V(j+1) overwrite / next P write
        if (j+1<16){ loadV(j+1); CP_COMMIT(); }
    }

    // ---- epilogue: normalize, split-write to g_attnsp ----
    #pragma unroll
    for (int mt=0;mt<2;mt++)
        #pragma unroll
        for (int hh=0;hh<2;hh++){
            float inv = 1.0f / lrow[mt][hh];
            int rg = bb_*NSEQ + q0 + wm*32 + mt*16 + (lane>>2) + 8*hh;
            #pragma unroll
            for (int nt=0;nt<4;nt++){
                int n = wn*32 + nt*8 + (lane&3)*2;
                float v0 = Oacc[mt][nt][2*hh]*inv, v1 = Oacc[mt][nt][2*hh+1]*inv;
                bf16 h0,l0,h1,l1; split2(v0,h0,l0); split2(v1,h1,l1);
                bf16* p = g_attnsp + (size_t)rg*(2*DM) + head*DH + n;
                *(bf162*)p      = bf162(h0,h1);
                *(bf162*)(p+DM) = bf162(l0,l1);
            }
        }
}

// ---------------- conversions / transposes (2-wide splits) ----------------
__global__ void k_trw3(const float* __restrict__ in, bf16* __restrict__ out, int R, int C){
    __shared__ float tile[32][33];
    const float* I = in + (size_t)blockIdx.z*R*C;
    bf16* O = out + (size_t)blockIdx.z*R*C*2;
    int r0=blockIdx.y*32, c0=blockIdx.x*32;
    int x=threadIdx.x, y=threadIdx.y;
    #pragma unroll
    for (int i=0;i<4;i++) tile[y+8*i][x] = I[(size_t)(r0+y+8*i)*C + c0+x];
    __syncthreads();
    #pragma unroll
    for (int i=0;i<4;i++){
        float v = tile[x][y+8*i];
        bf16 hi, lo; split2(v, hi, lo);
        bf16* p = O + (size_t)(c0+y+8*i)*2*R + r0+x;
        p[0] = hi; p[R] = lo;
    }
}

__global__ void k_cvt_qk(){
    int gid = blockIdx.x*blockDim.x + threadIdx.x;   // TTOK*512
    int t = gid >> 9, c = gid & 511;
    int h = c >> 6, d = c & 63;
    int b = t >> 10, n = t & 1023;
    size_t base = ((size_t)(b*8+h)*NSEQ + n)*(2*DH);
    float qv = g_qkv[(size_t)t*QKVN + c];
    float kv = g_qkv[(size_t)t*QKVN + 512 + c];
    bf16 qh,ql,kh,kl; split2(qv,qh,ql); split2(kv,kh,kl);
    g_qh[base + d] = qh; g_qh[base + 64 + d] = ql;
    g_kh[base + d] = kh; g_kh[base + 64 + d] = kl;
}

__global__ void k_trv3(){
    __shared__ float tile[32][33];
    int bh=blockIdx.z, b=bh>>3, h=bh&7;
    const float* I = g_qkv + (size_t)b*NSEQ*QKVN + 1024 + h*DH;
    bf16* O = g_vth + (size_t)bh*DH*2*NSEQ;
    int n0=blockIdx.y*32, d0=blockIdx.x*32;
    int x=threadIdx.x, y=threadIdx.y;
    #pragma unroll
    for (int i=0;i<4;i++) tile[y+8*i][x] = I[(size_t)(n0+y+8*i)*QKVN + d0+x];
    __syncthreads();
    #pragma unroll
    for (int i=0;i<4;i++){
        float v = tile[x][y+8*i];
        bf16 hi, lo; split2(v, hi, lo);
        bf16* p = O + (size_t)(d0+y+8*i)*2*NSEQ + n0+x;
        p[0] = hi; p[NSEQ] = lo;
    }
}

// ---------------- elementwise / routing ----------------
__global__ void k_copy4(const float4* __restrict__ in, float4* __restrict__ out, int n4){
    int i = blockIdx.x*blockDim.x + threadIdx.x;
    if (i < n4) out[i] = in[i];
}

template<int F32OUT>
__global__ void k_ln_h(const float* __restrict__ in, bf16* __restrict__ outh,
                       float* __restrict__ outf,
                       const float* __restrict__ w, const float* __restrict__ b){
    int t = blockIdx.x, i = threadIdx.x;
    float4 v = ((const float4*)(in + (size_t)t*DM))[i];
    float s  = v.x+v.y+v.z+v.w;
    float ss = v.x*v.x+v.y*v.y+v.z*v.z+v.w*v.w;
    #pragma unroll
    for (int o=16;o;o>>=1){ s += __shfl_xor_sync(0xffffffffu,s,o); ss += __shfl_xor_sync(0xffffffffu,ss,o); }
    __shared__ float sh_s[4], sh_q[4];
    int wid = i>>5, lane = i&31;
    if (lane==0){ sh_s[wid]=s; sh_q[wid]=ss; }
    __syncthreads();
    s  = sh_s[0]+sh_s[1]+sh_s[2]+sh_s[3];
    ss = sh_q[0]+sh_q[1]+sh_q[2]+sh_q[3];
    float mean = s * (1.0f/DM);
    float var  = ss * (1.0f/DM) - mean*mean;
    float inv  = rsqrtf(var + 1e-5f);
    float4 wv = ((const float4*)w)[i];
    float4 bv = ((const float4*)b)[i];
    float4 o;
    o.x=(v.x-mean)*inv*wv.x+bv.x; o.y=(v.y-mean)*inv*wv.y+bv.y;
    o.z=(v.z-mean)*inv*wv.z+bv.z; o.w=(v.w-mean)*inv*wv.w+bv.w;
    bf16* p = outh + (size_t)t*2*DM + 4*i;
    bf16 h0,l0,h1,l1,h2,l2,h3,l3;
    split2(o.x,h0,l0); split2(o.y,h1,l1); split2(o.z,h2,l2); split2(o.w,h3,l3);
    *(bf162*)(p)      = bf162(h0,h1); *(bf162*)(p+2)      = bf162(h2,h3);
    *(bf162*)(p+DM)   = bf162(l0,l1); *(bf162*)(p+DM+2)   = bf162(l2,l3);
    if (F32OUT) ((float4*)(outf + (size_t)t*DM))[i] = o;
}

__global__ void k_ln_f(const float* __restrict__ in, float* __restrict__ out,
                       const float* __restrict__ w, const float* __restrict__ b){
    int t = blockIdx.x, i = threadIdx.x;
    float4 v = ((const float4*)(in + (size_t)t*DM))[i];
    float s  = v.x+v.y+v.z+v.w;
    float ss = v.x*v.x+v.y*v.y+v.z*v.z+v.w*v.w;
    #pragma unroll
    for (int o=16;o;o>>=1){ s += __shfl_xor_sync(0xffffffffu,s,o); ss += __shfl_xor_sync(0xffffffffu,ss,o); }
    __shared__ float sh_s[4], sh_q[4];
    int wid = i>>5, lane = i&31;
    if (lane==0){ sh_s[wid]=s; sh_q[wid]=ss; }
    __syncthreads();
    s  = sh_s[0]+sh_s[1]+sh_s[2]+sh_s[3];
    ss = sh_q[0]+sh_q[1]+sh_q[2]+sh_q[3];
    float mean = s * (1.0f/DM);
    float var  = ss * (1.0f/DM) - mean*mean;
    float inv  = rsqrtf(var + 1e-5f);
    float4 wv = ((const float4*)w)[i];
    float4 bv = ((const float4*)b)[i];
    float4 o;
    o.x=(v.x-mean)*inv*wv.x+bv.x; o.y=(v.y-mean)*inv*wv.y+bv.y;
    o.z=(v.z-mean)*inv*wv.z+bv.z; o.w=(v.w-mean)*inv*wv.w+bv.w;
    ((float4*)(out + (size_t)t*DM))[i] = o;
}

__global__ void k_gate(const float* __restrict__ wg){
    int gid = blockIdx.x*blockDim.x + threadIdx.x;
    if (gid >= TTOK*NE) return;
    int t = gid>>3, e = gid&7;
    const float* xr = g_y + (size_t)t*DM;
    float s = 0.f;
    #pragma unroll 8
    for (int k=0;k<DM;k++) s = fmaf(xr[k], wg[k*NE+e], s);
    g_logits[t*NE+e] = s;
}

__global__ void k_zero_cnt(){ if (threadIdx.x < NE) g_cnt[threadIdx.x] = 0; }

__global__ void k_top2(){
    int t = blockIdx.x*blockDim.x + threadIdx.x;
    if (t >= TTOK) return;
    const float* lr = g_logits + t*NE;
    int i0 = 0; float v0 = lr[0];
    #pragma unroll
    for (int e=1;e<NE;e++){ float v = lr[e]; if (v > v0){ v0=v; i0=e; } }
    int i1 = -1; float v1 = -3.4e38f;
    #pragma unroll
    for (int e=0;e<NE;e++){ if (e==i0) continue; float v = lr[e]; if (v > v1){ v1=v; i1=e; } }
    float e1v = expf(v1 - v0);
    float inv = 1.0f/(1.0f + e1v);
    g_e0[t]=i0; g_e1i[t]=i1;
    g_g0[t]=inv; g_g1[t]=e1v*inv;
    atomicAdd(&g_cnt[i0],1);
    atomicAdd(&g_cnt[i1],1);
}

__global__ void k_scan(){
    int off = 0, rb = 0;
    for (int e=0;e<NE;e++){
        g_off[e] = off; g_cur[e] = off;
        int nb = (g_cnt[e] + 127) >> 7;
        for (int i=0;i<nb;i++) g_map[rb++] = e;
        off += nb*128;
    }
    for (; rb<MAXRB; rb++) g_map[rb] = -1;
}

__global__ void k_scatter(){
    int t = blockIdx.x*blockDim.x + threadIdx.x;
    if (t >= TTOK) return;
    int p0 = atomicAdd(&g_cur[g_e0[t]], 1);  g_tok[p0]=t; g_slotA[t]=p0;
    int p1 = atomicAdd(&g_cur[g_e1i[t]], 1); g_tok[p1]=t; g_slotB[t]=p1;
}

__global__ void k_combine(){
    int t = blockIdx.x, i = threadIdx.x;
    float gg0 = g_g0[t], gg1 = g_g1[t];
    float4 a = ((const float4*)(g_y2 + (size_t)g_slotA[t]*DM))[i];
    float4 b = ((const float4*)(g_y2 + (size_t)g_slotB[t]*DM))[i];
    float4* xr = (float4*)(g_x + (size_t)t*DM);
    float4 xv = xr[i];
    xv.x += gg0*a.x + gg1*b.x;
    xv.y += gg0*a.y + gg1*b.y;
    xv.z += gg0*a.z + gg1*b.z;
    xv.w += gg0*a.w + gg1*b.w;
    xr[i] = xv;
}

// ---------------- host orchestration ----------------
#define SMEM128 (3*(16384 + 128*128))   /* 98304 */

extern "C" void kernel_launch(void* const* d_in, const int* in_sizes, int n_in,
                              void* d_out, int out_size){
    (void)in_sizes; (void)n_in; (void)out_size;
    const float* x    = (const float*)d_in[0];
    const float* ln1w = (const float*)d_in[1];
    const float* ln1b = (const float*)d_in[2];
    const float* qkvw = (const float*)d_in[3];
    const float* outw = (const float*)d_in[4];
    const float* outb = (const float*)d_in[5];
    const float* ln2w = (const float*)d_in[6];
    const float* ln2b = (const float*)d_in[7];
    const float* wg   = (const float*)d_in[8];
    const float* ew1  = (const float*)d_in[9];
    const float* eb1  = (const float*)d_in[10];
    const float* ew2  = (const float*)d_in[11];
    const float* eb2  = (const float*)d_in[12];
    const float* flnw = (const float*)d_in[13];
    const float* flnb = (const float*)d_in[14];
    float* out = (float*)d_out;

    float *px, *py, *pq, *py2;
    bf16 *pyh, *phh, *pattnsp, *pqkvT, *poutT, *pe1T, *pe2T;
    cudaGetSymbolAddress((void**)&px,   g_x);
    cudaGetSymbolAddress((void**)&py,   g_y);
    cudaGetSymbolAddress((void**)&pq,   g_qkv);
    cudaGetSymbolAddress((void**)&py2,  g_y2);
    cudaGetSymbolAddress((void**)&pyh,  g_yh);
    cudaGetSymbolAddress((void**)&phh,  g_hh);
    cudaGetSymbolAddress((void**)&pattnsp, g_attnsp);
    cudaGetSymbolAddress((void**)&pqkvT,g_qkvwT);
    cudaGetSymbolAddress((void**)&poutT,g_outwT);
    cudaGetSymbolAddress((void**)&pe1T, g_e1T);
    cudaGetSymbolAddress((void**)&pe2T, g_e2T);

    cudaFuncSetAttribute(k_mma<1>, cudaFuncAttributeMaxDynamicSharedMemorySize, SMEM128);
    cudaFuncSetAttribute(k_mma<3>, cudaFuncAttributeMaxDynamicSharedMemorySize, SMEM128);
    cudaFuncSetAttribute(k_flash, cudaFuncAttributeMaxDynamicSharedMemorySize, FSMEM);
    cudaFuncSetAttribute(k_moe_mma<4,1>, cudaFuncAttributeMaxDynamicSharedMemorySize, SMEM128);
    cudaFuncSetAttribute(k_moe_mma<5,0>, cudaFuncAttributeMaxDynamicSharedMemorySize, SMEM128);

    {   int n4 = TTOK*DM/4;
        k_copy4<<<(n4+255)/256, 256>>>((const float4*)x, (float4*)px, n4); }

    // weight transpose + 2-wide bf16 split
    k_trw3<<<dim3(QKVN/32, DM/32, NL), dim3(32,8)>>>(qkvw, pqkvT, DM, QKVN);
    k_trw3<<<dim3(DM/32,   DM/32, NL), dim3(32,8)>>>(outw, poutT, DM, DM);
    k_trw3<<<dim3(HFF/32,  DM/32, NL*NE), dim3(32,8)>>>(ew1, pe1T, DM, HFF);
    k_trw3<<<dim3(DM/32,  HFF/32, NL*NE), dim3(32,8)>>>(ew2, pe2T, HFF, DM);

    for (int l=0;l<NL;l++){
        // ---- attention ----
        k_ln_h<0><<<TTOK,128>>>(px, pyh, (float*)0, ln1w + l*DM, ln1b + l*DM);
        k_mma<1><<<dim3(QKVN/128, TTOK/128), 256, SMEM128>>>(
            pyh, 2*DM, pqkvT + (size_t)l*QKVN*2*DM, 2*DM, pq, QKVN,
            (const float*)0, 3*DM, 1.f, DM/64, DM/64);
        k_cvt_qk<<<(TTOK*512)/256, 256>>>();
        k_trv3<<<dim3(2, NSEQ/32, 64), dim3(32,8)>>>();
        k_flash<<<dim3(NSEQ/128, 64), 256, FSMEM>>>();
        k_mma<3><<<dim3(DM/128, TTOK/128), 256, SMEM128>>>(
            pattnsp, 2*DM, poutT + (size_t)l*DM*2*DM, 2*DM, px, DM,
            outb + l*DM, 3*DM, 1.f, DM/64, DM/64);
        // ---- MoE ----
        k_ln_h<1><<<TTOK,128>>>(px, pyh, py, ln2w + l*DM, ln2b + l*DM);
        k_zero_cnt<<<1,32>>>();
        k_gate<<<(TTOK*NE)/256, 256>>>(wg + (size_t)l*DM*NE);
        k_top2<<<TTOK/256, 256>>>();
        k_scan<<<1,1>>>();
        k_scatter<<<TTOK/256, 256>>>();
        k_moe_mma<4,1><<<dim3(HFF/128, MAXRB), 256, SMEM128>>>(
            pyh, 2*DM, pe1T + (size_t)l*NE*HFF*2*DM, 2*DM, phh, 2*HFF,
            eb1 + (size_t)l*NE*HFF, 3*DM, HFF, HFF, DM/64, DM/64);
        k_moe_mma<5,0><<<dim3(DM/128, MAXRB), 256, SMEM128>>>(
            phh, 2*HFF, pe2T + (size_t)l*NE*DM*2*HFF, 2*HFF, py2, DM,
            eb2 + (size_t)l*NE*DM, 3*HFF, DM, 0, HFF/64, HFF/64);
        k_combine<<<TTOK,128>>>();
    }

    k_ln_f<<<TTOK,128>>>(px, out, flnw, flnb);
}